// round 8
// baseline (speedup 1.0000x reference)
#include <cuda_runtime.h>
#include <cuda_bf16.h>
#include <cstdint>

#define HW 65536
#define EPSN 1e-12f

typedef unsigned long long u64;

// ---------------- scratch (static device globals; no allocation) ----------------
__device__ unsigned g_qmb[16777216]; // [8][64][32768] bf16-pair qm
__device__ unsigned g_kvl[16777216]; // [8][64][32768] bf16-pair kvm low (k source)
__device__ float    g_kvh[33554432]; // [8][64][65536] f32 kvm high (v source)
__device__ float    g_v  [33554432]; // [8][64][65536] v after dwconv
__device__ unsigned g_qb [16777216]; // [8][64][32768] bf16 q_dw
__device__ unsigned g_kb [16777216]; // [8][64][32768] bf16 k_dw
__device__ float g_gram[8192];       // [8][4][16][16]
__device__ float g_qss[512];         // [8][64]
__device__ float g_kss[512];         // [8][64]

// ---------------- f32x2 helpers ----------------
__device__ __forceinline__ u64 pk2(float lo, float hi){
    u64 r; asm("mov.b64 %0, {%1, %2};" : "=l"(r) : "f"(lo), "f"(hi)); return r;
}
__device__ __forceinline__ void upk2(u64 v, float& lo, float& hi){
    asm("mov.b64 {%0, %1}, %2;" : "=f"(lo), "=f"(hi) : "l"(v));
}
__device__ __forceinline__ u64 ffma2(u64 a, u64 b, u64 c){
    u64 d; asm("fma.rn.f32x2 %0, %1, %2, %3;" : "=l"(d) : "l"(a), "l"(b), "l"(c)); return d;
}
__device__ __forceinline__ void fma_bcast(u64 (&acc)[2], float w, const u64 (&p)[2]){
    u64 wp = pk2(w, w);
    acc[0] = ffma2(wp, p[0], acc[0]);
    acc[1] = ffma2(wp, p[1], acc[1]);
}
__device__ __forceinline__ float bflo(unsigned u){ return __int_as_float((int)(u << 16)); }
__device__ __forceinline__ float bfhi(unsigned u){ return __int_as_float((int)(u & 0xffff0000u)); }
__device__ __forceinline__ unsigned pkbf(float a, float b){
    __nv_bfloat162 p = __floats2bfloat162_rn(a, b);
    return *(unsigned*)&p;
}

// ---------------- cp.async helpers ----------------
__device__ __forceinline__ void cpa16(void* smem, const void* g){
    unsigned s = (unsigned)__cvta_generic_to_shared(smem);
    asm volatile("cp.async.cg.shared.global [%0], [%1], 16;" :: "r"(s), "l"(g));
}
__device__ __forceinline__ void cpa_commit(){ asm volatile("cp.async.commit_group;"); }
__device__ __forceinline__ void cpa_wait1(){ asm volatile("cp.async.wait_group 1;"); }

// ---------------- warp mma (arch-generic bf16 HMMA) ----------------
__device__ __forceinline__ void mma16816(float* c, const unsigned* a, const unsigned* b){
    asm volatile("mma.sync.aligned.m16n8k16.row.col.f32.bf16.bf16.f32 "
        "{%0,%1,%2,%3}, {%4,%5,%6,%7}, {%8,%9}, {%0,%1,%2,%3};"
        : "+f"(c[0]), "+f"(c[1]), "+f"(c[2]), "+f"(c[3])
        : "r"(a[0]), "r"(a[1]), "r"(a[2]), "r"(a[3]), "r"(b[0]), "r"(b[1]));
}

// ---------------- K0: zero the accumulators (every replay) ----------------
__global__ void k0_init(){
    int i = blockIdx.x * 256 + threadIdx.x;
    if (i < 8192) g_gram[i] = 0.f;
    if (i < 512){ g_qss[i] = 0.f; g_kss[i] = 0.f; }
}

#define NTILES 4096   // 128-px tiles over 8 batches x 65536 px
#define ROWW 36       // bf16 smem row stride in 32-bit words (72 bf16, padded)

// ---------------- K1: fused q-path (mma) + kv-path (fma), parity-interleaved ----------------
// even blocks: kv path (smem: sW 8192f + 2x8192f stages = 98304B)
// odd  blocks: q path  (smem: sD/sX 2x128x36 words = 36864B)
__global__ void __launch_bounds__(256, 2) k1_fused(
    const float* __restrict__ dg, const float* __restrict__ xin,
    const float* __restrict__ yin,
    const float* __restrict__ q1w, const float* __restrict__ q2w,
    const float* __restrict__ kvw)
{
    extern __shared__ __align__(16) char smraw[];
    const int tid = threadIdx.x;
    const int vstride = gridDim.x >> 1;
    const int vid = blockIdx.x >> 1;

    if (blockIdx.x & 1){
        // ================= q path (R6 k1a_mma) =================
        unsigned* smk = (unsigned*)smraw;
        unsigned* sD = smk;
        unsigned* sX = smk + 128*ROWW;
        const int wid = tid >> 5, lane = tid & 31;
        const int mb = wid & 3, nh = wid >> 2;
        const int grow = lane >> 2, t = lane & 3;

        unsigned aW1[4][4], aW2[4][4];
        {
            const int r0 = mb*16 + grow;
            #pragma unroll
            for (int cc = 0; cc < 4; ++cc){
                const int k0 = cc*16 + t*2;
                aW1[cc][0] = pkbf(__ldg(q1w + r0*64 + k0),       __ldg(q1w + r0*64 + k0 + 1));
                aW1[cc][1] = pkbf(__ldg(q1w + (r0+8)*64 + k0),   __ldg(q1w + (r0+8)*64 + k0 + 1));
                aW1[cc][2] = pkbf(__ldg(q1w + r0*64 + k0 + 8),   __ldg(q1w + r0*64 + k0 + 9));
                aW1[cc][3] = pkbf(__ldg(q1w + (r0+8)*64 + k0+8), __ldg(q1w + (r0+8)*64 + k0 + 9));
                aW2[cc][0] = pkbf(__ldg(q2w + r0*64 + k0),       __ldg(q2w + r0*64 + k0 + 1));
                aW2[cc][1] = pkbf(__ldg(q2w + (r0+8)*64 + k0),   __ldg(q2w + (r0+8)*64 + k0 + 1));
                aW2[cc][2] = pkbf(__ldg(q2w + r0*64 + k0 + 8),   __ldg(q2w + r0*64 + k0 + 9));
                aW2[cc][3] = pkbf(__ldg(q2w + (r0+8)*64 + k0+8), __ldg(q2w + (r0+8)*64 + k0 + 9));
            }
        }

        auto cvt = [&](const float* gsrc, unsigned* sT){
            #pragma unroll
            for (int j = 0; j < 8; ++j){
                const int idx = tid + j*256;
                const int ch = idx & 63;
                const int px0 = (idx >> 6) << 2;
                float4 v = __ldg((const float4*)(gsrc + (size_t)ch*HW + px0));
                float o0 = __shfl_xor_sync(0xffffffffu, v.x, 1);
                float o1 = __shfl_xor_sync(0xffffffffu, v.y, 1);
                float o2 = __shfl_xor_sync(0xffffffffu, v.z, 1);
                float o3 = __shfl_xor_sync(0xffffffffu, v.w, 1);
                const int cp = ch >> 1;
                if (!(ch & 1)){
                    sT[(px0    )*ROWW + cp] = pkbf(v.x, o0);
                    sT[(px0 + 1)*ROWW + cp] = pkbf(v.y, o1);
                } else {
                    sT[(px0 + 2)*ROWW + cp] = pkbf(o2, v.z);
                    sT[(px0 + 3)*ROWW + cp] = pkbf(o3, v.w);
                }
            }
        };

        for (int tt = vid; tt < NTILES; tt += vstride){
            const int bb = tt >> 9;
            const size_t pxb = (size_t)(tt & 511) << 7;

            cvt(dg  + (size_t)bb*64*HW + pxb, sD);
            cvt(xin + (size_t)bb*64*HW + pxb, sX);
            __syncthreads();

            const int pxw0 = (int)(pxb >> 1);
            #pragma unroll
            for (int nt = 0; nt < 8; ++nt){
                const int nb = nh*64 + nt*8;
                const int nrow = nb + grow;
                float ac1[4] = {0.f, 0.f, 0.f, 0.f};
                float ac2[4] = {0.f, 0.f, 0.f, 0.f};
                #pragma unroll
                for (int cc = 0; cc < 4; ++cc){
                    unsigned bD[2], bX[2];
                    const int w0 = nrow*ROWW + cc*8 + t;
                    bD[0] = sD[w0]; bD[1] = sD[w0 + 4];
                    bX[0] = sX[w0]; bX[1] = sX[w0 + 4];
                    mma16816(ac1, aW1[cc], bD);
                    mma16816(ac2, aW2[cc], bX);
                }
                const int ch = bb*64 + mb*16 + grow;
                const int pxp = pxw0 + (nb >> 1) + t;
                g_qmb[(size_t)ch*32768 + pxp]       = pkbf(ac1[0]*ac2[0], ac1[1]*ac2[1]);
                g_qmb[(size_t)(ch + 8)*32768 + pxp] = pkbf(ac1[2]*ac2[2], ac1[3]*ac2[3]);
            }
            __syncthreads();
        }
    } else {
        // ================= kv path (R6 k1b_kv) =================
        float* sm = (float*)smraw;
        float* sW  = sm;
        float* buf = sm + 8192;
        const int tx = tid & 31, ty = tid >> 5;

        for (int i = tid; i < 2048; i += 256)
            *(float4*)(sW + (i<<2)) = *(const float4*)(kvw + (i<<2));

        auto issue = [&](int t, int s){
            if (t < NTILES){
                const int b = t >> 9; const size_t base = (size_t)(t & 511) << 7;
                const float* gy = yin + (size_t)b*64*HW + base;
                float* sY = buf + s*8192;
                #pragma unroll
                for (int i = tid; i < 2048; i += 256){
                    const int c = i >> 5, off = (i & 31) << 2;
                    cpa16(sY + c*128 + off, gy + (size_t)c*HW + off);
                }
            }
            cpa_commit();
        };

        int s = 0;
        issue(vid, 0);
        for (int t = vid; t < NTILES; t += vstride){
            issue(t + vstride, s ^ 1);
            cpa_wait1();
            __syncthreads();

            const float* sY = buf + s*8192;
            u64 av[16][2];
            #pragma unroll
            for (int i = 0; i < 16; ++i){ av[i][0]=av[i][1]=0ull; }

            #pragma unroll 4
            for (int k0 = 0; k0 < 64; k0 += 4){
                u64 yP[4][2];
                #pragma unroll
                for (int kk = 0; kk < 4; ++kk){
                    float4 y4 = *(const float4*)(sY + (k0+kk)*128 + (tx<<2));
                    yP[kk][0] = pk2(y4.x, y4.y); yP[kk][1] = pk2(y4.z, y4.w);
                }
                #pragma unroll
                for (int i = 0; i < 16; ++i){
                    const int o = ty + (i<<3);
                    float4 w = *(const float4*)(sW + o*64 + k0);
                    fma_bcast(av[i], w.x, yP[0]); fma_bcast(av[i], w.y, yP[1]);
                    fma_bcast(av[i], w.z, yP[2]); fma_bcast(av[i], w.w, yP[3]);
                }
            }
            const int b = t >> 9; const size_t base = (size_t)(t & 511) << 7;
            #pragma unroll
            for (int i = 0; i < 8; ++i){     // k channels -> bf16
                const int o = ty + (i<<3);
                float4 r; upk2(av[i][0], r.x, r.y); upk2(av[i][1], r.z, r.w);
                uint2 u; u.x = pkbf(r.x, r.y); u.y = pkbf(r.z, r.w);
                *(uint2*)(g_kvl + (((size_t)(b*64 + o))*HW + base + (tx<<2) >> 1)) = u;
            }
            #pragma unroll
            for (int i = 8; i < 16; ++i){    // v channels -> f32
                const int o = ty + ((i - 8)<<3);
                float4 r; upk2(av[i][0], r.x, r.y); upk2(av[i][1], r.z, r.w);
                *(float4*)(g_kvh + ((size_t)(b*64 + o))*HW + base + (tx<<2)) = r;
            }
            __syncthreads();
            s ^= 1;
        }
    }
}

// ---------------- K2a: depthwise 3x3, one channel-plane per block ----------------
__global__ void __launch_bounds__(256) k2a_dw(
    const float* __restrict__ qdw, const float* __restrict__ kvdw)
{
    const int b = blockIdx.z, plane = blockIdx.y, band = blockIdx.x;
    const int kind = plane >> 6;           // 0=q, 1=k, 2=v
    const int c = plane & 63;

    const float* w9;
    const unsigned* srcb = nullptr; const float* srcf = nullptr;
    if (kind == 0){ srcb = g_qmb + (((size_t)(b*64 + c))*HW >> 1); w9 = qdw  + c*9; }
    else if (kind == 1){ srcb = g_kvl + (((size_t)(b*64 + c))*HW >> 1); w9 = kvdw + c*9; }
    else { srcf = g_kvh + ((size_t)(b*64 + c))*HW; w9 = kvdw + (64 + c)*9; }

    float w[9];
    #pragma unroll
    for (int i = 0; i < 9; ++i) w[i] = __ldg(w9 + i);

    const int tid = threadIdx.x;
    const int rg = tid >> 6, xq = tid & 63, xx = xq << 2;
    const int lane = tid & 31;
    const int y0 = band*16 + rg*4;

    float4 o[4];
    #pragma unroll
    for (int j = 0; j < 4; ++j) o[j] = make_float4(0.f, 0.f, 0.f, 0.f);

    #pragma unroll
    for (int i = 0; i < 6; ++i){
        const int ys = y0 - 1 + i;
        const bool yok = (ys >= 0) && (ys <= 255);
        float4 c4 = make_float4(0.f, 0.f, 0.f, 0.f);
        float lv, rv;
        if (kind == 2){
            const float* row = srcf + ys*256 + xx;
            if (yok) c4 = __ldg((const float4*)row);
            lv = __shfl_up_sync(0xffffffffu, c4.w, 1);
            rv = __shfl_down_sync(0xffffffffu, c4.x, 1);
            if (lane == 0)  lv = (yok && xx > 0)   ? __ldg(row - 1) : 0.f;
            if (lane == 31) rv = (yok && xx < 252) ? __ldg(row + 4) : 0.f;
        } else {
            const unsigned* row = srcb + (ys << 7) + (xx >> 1);
            if (yok){
                uint2 u = __ldg((const uint2*)row);
                c4.x = bflo(u.x); c4.y = bfhi(u.x); c4.z = bflo(u.y); c4.w = bfhi(u.y);
            }
            lv = __shfl_up_sync(0xffffffffu, c4.w, 1);
            rv = __shfl_down_sync(0xffffffffu, c4.x, 1);
            if (lane == 0)  lv = (yok && xx > 0)   ? bfhi(__ldg(row - 1)) : 0.f;
            if (lane == 31) rv = (yok && xx < 252) ? bflo(__ldg(row + 2)) : 0.f;
        }

        #pragma unroll
        for (int j = 0; j < 4; ++j){
            const int ky = i - j;
            if (ky >= 0 && ky < 3){
                const float wa = w[ky*3], wb = w[ky*3+1], wc = w[ky*3+2];
                o[j].x += wa*lv   + wb*c4.x + wc*c4.y;
                o[j].y += wa*c4.x + wb*c4.y + wc*c4.z;
                o[j].z += wa*c4.y + wb*c4.z + wc*c4.w;
                o[j].w += wa*c4.z + wb*c4.w + wc*rv;
            }
        }
    }

    const size_t obase = ((size_t)(b*64 + c))*HW + (size_t)y0*256 + xx;

    if (kind == 2){
        #pragma unroll
        for (int j = 0; j < 4; ++j)
            *(float4*)(g_v + obase + j*256) = o[j];
        return;
    }

    float s = 0.f;
    #pragma unroll
    for (int j = 0; j < 4; ++j)
        s += o[j].x*o[j].x + o[j].y*o[j].y + o[j].z*o[j].z + o[j].w*o[j].w;
    #pragma unroll
    for (int off = 16; off; off >>= 1) s += __shfl_xor_sync(0xffffffffu, s, off);
    if (lane == 0)
        atomicAdd((kind == 0 ? g_qss : g_kss) + b*64 + c, s);

    unsigned* dst = (kind == 0 ? g_qb : g_kb);
    #pragma unroll
    for (int j = 0; j < 4; ++j){
        uint2 u;
        u.x = pkbf(o[j].x, o[j].y);
        u.y = pkbf(o[j].z, o[j].w);
        *(uint2*)(dst + ((obase + (size_t)j*256) >> 1)) = u;
    }
}

// ---------------- K2b: gram = q_dw @ k_dw^T (bf16 in, f32 acc) ----------------
__global__ void __launch_bounds__(256) k2b_gram()
{
    const int b = blockIdx.z, h = blockIdx.y, chunk = blockIdx.x;
    const int tid = threadIdx.x;
    const int g = tid >> 4, it = (tid >> 2) & 3, jt = tid & 3;
    const int p0 = chunk*4096 + g*256;

    const unsigned* qb = g_qb + (((size_t)(b*64 + h*16)) * HW >> 1);
    const unsigned* kb = g_kb + (((size_t)(b*64 + h*16)) * HW >> 1);

    float acc[4][4];
    #pragma unroll
    for (int a = 0; a < 4; ++a)
        #pragma unroll
        for (int d = 0; d < 4; ++d) acc[a][d] = 0.f;

    for (int p = p0; p < p0 + 256; p += 8){
        uint4 qu[4], ku[4];
        #pragma unroll
        for (int a = 0; a < 4; ++a){
            qu[a] = __ldg((const uint4*)(qb + (((size_t)(it*4 + a))*HW + p >> 1)));
            ku[a] = __ldg((const uint4*)(kb + (((size_t)(jt*4 + a))*HW + p >> 1)));
        }
        float qf[4][8], kf[4][8];
        #pragma unroll
        for (int a = 0; a < 4; ++a){
            qf[a][0]=bflo(qu[a].x); qf[a][1]=bfhi(qu[a].x);
            qf[a][2]=bflo(qu[a].y); qf[a][3]=bfhi(qu[a].y);
            qf[a][4]=bflo(qu[a].z); qf[a][5]=bfhi(qu[a].z);
            qf[a][6]=bflo(qu[a].w); qf[a][7]=bfhi(qu[a].w);
            kf[a][0]=bflo(ku[a].x); kf[a][1]=bfhi(ku[a].x);
            kf[a][2]=bflo(ku[a].y); kf[a][3]=bfhi(ku[a].y);
            kf[a][4]=bflo(ku[a].z); kf[a][5]=bfhi(ku[a].z);
            kf[a][6]=bflo(ku[a].w); kf[a][7]=bfhi(ku[a].w);
        }
        #pragma unroll
        for (int a = 0; a < 4; ++a)
            #pragma unroll
            for (int d = 0; d < 4; ++d){
                float t = 0.f;
                #pragma unroll
                for (int px = 0; px < 8; ++px) t += qf[a][px]*kf[d][px];
                acc[a][d] += t;
            }
    }
    #pragma unroll
    for (int a = 0; a < 4; ++a)
        #pragma unroll
        for (int d = 0; d < 4; ++d)
            atomicAdd(g_gram + (b*4 + h)*256 + (it*4 + a)*16 + (jt*4 + d), acc[a][d]);
}

// ---------------- K4: per-batch blocks; prologue computes M = proj∘softmax, then M@v ----------------
// smem: sV 2x8192f (65536B) | sM 4096f (16384B) | sA 1024f (4096B) = 86016B
__global__ void __launch_bounds__(256, 2) k4_out(
    float* __restrict__ out,
    const float* __restrict__ pjw, const float* __restrict__ temp)
{
    extern __shared__ float sm[];
    float* buf = sm;            // 2 stages x 8192
    float* sM  = sm + 16384;    // 4096
    float* sA  = sm + 20480;    // 1024
    const int tid = threadIdx.x, tx = tid & 31, ty = tid >> 5;
    const int b = blockIdx.x & 7;
    const int sub = blockIdx.x >> 3;        // 0..37
    const int bstride = gridDim.x >> 3;     // 38

    // ---- prologue: softmax attn + fold proj -> sM ----
    if (tid < 64){
        const int h = tid >> 4;
        const float t = __ldg(temp + h);
        const float inq = t / fmaxf(sqrtf(g_qss[b*64 + tid]), EPSN);
        const float* gr = g_gram + (b*4 + h)*256 + (tid & 15)*16;
        float l[16]; float mx = -1e30f;
        #pragma unroll
        for (int d = 0; d < 16; ++d){
            l[d] = gr[d] * inq / fmaxf(sqrtf(g_kss[b*64 + h*16 + d]), EPSN);
            mx = fmaxf(mx, l[d]);
        }
        float ssum = 0.f;
        #pragma unroll
        for (int d = 0; d < 16; ++d){ l[d] = __expf(l[d] - mx); ssum += l[d]; }
        const float inv = 1.f / ssum;
        #pragma unroll
        for (int d = 0; d < 16; ++d) sA[tid*16 + d] = l[d] * inv;
    }
    __syncthreads();
    for (int idx = tid; idx < 4096; idx += 256){
        const int o = idx >> 6, cd = idx & 63, h = cd >> 4, d = cd & 15;
        float s = 0.f;
        #pragma unroll
        for (int ci = 0; ci < 16; ++ci)
            s += __ldg(pjw + o*64 + h*16 + ci) * sA[(h*16 + ci)*16 + d];
        sM[idx] = s;
    }
    __syncthreads();

    // ---- main loop: 512 in-batch tiles, stride 38, double-buffered sV ----
    auto issue = [&](int t, int s){
        if (t < 512){
            const size_t base = (size_t)t << 7;
            const float* gv = g_v + (size_t)b*64*HW + base;
            float* sV = buf + s*8192;
            #pragma unroll
            for (int i = tid; i < 2048; i += 256){
                const int c = i >> 5, off = (i & 31) << 2;
                cpa16(sV + c*128 + off, gv + (size_t)c*HW + off);
            }
        }
        cpa_commit();
    };

    int s = 0;
    issue(sub, 0);
    for (int t = sub; t < 512; t += bstride){
        issue(t + bstride, s ^ 1);
        cpa_wait1();
        __syncthreads();

        const float* sV = buf + s*8192;
        u64 acc[8][2];
        #pragma unroll
        for (int i = 0; i < 8; ++i){ acc[i][0] = acc[i][1] = 0ull; }

        #pragma unroll 4
        for (int k0 = 0; k0 < 64; k0 += 4){
            u64 vP[4][2];
            #pragma unroll
            for (int kk = 0; kk < 4; ++kk){
                float4 v4 = *(const float4*)(sV + (k0+kk)*128 + (tx<<2));
                vP[kk][0] = pk2(v4.x, v4.y); vP[kk][1] = pk2(v4.z, v4.w);
            }
            #pragma unroll
            for (int i = 0; i < 8; ++i){
                float4 w = *(const float4*)(sM + (ty + (i<<3))*64 + k0);
                fma_bcast(acc[i], w.x, vP[0]); fma_bcast(acc[i], w.y, vP[1]);
                fma_bcast(acc[i], w.z, vP[2]); fma_bcast(acc[i], w.w, vP[3]);
            }
        }
        const size_t base = (size_t)t << 7;
        #pragma unroll
        for (int i = 0; i < 8; ++i){
            const int o = ty + (i<<3);
            float4 r; upk2(acc[i][0], r.x, r.y); upk2(acc[i][1], r.z, r.w);
            *(float4*)(out + ((size_t)(b*64 + o))*HW + base + (tx<<2)) = r;
        }
        __syncthreads();
        s ^= 1;
    }
}

// ---------------- launch ----------------
extern "C" void kernel_launch(void* const* d_in, const int* in_sizes, int n_in,
                              void* d_out, int out_size)
{
    (void)in_sizes; (void)n_in; (void)out_size;
    const float* dg   = (const float*)d_in[0];
    const float* xin  = (const float*)d_in[1];
    const float* yin  = (const float*)d_in[2];
    const float* q1w  = (const float*)d_in[3];
    const float* q2w  = (const float*)d_in[4];
    const float* qdw  = (const float*)d_in[5];
    const float* kvw  = (const float*)d_in[6];
    const float* kvdw = (const float*)d_in[7];
    const float* pjw  = (const float*)d_in[8];
    const float* temp = (const float*)d_in[9];
    float* out = (float*)d_out;

    cudaFuncSetAttribute(k1_fused, cudaFuncAttributeMaxDynamicSharedMemorySize, 98304);
    cudaFuncSetAttribute(k4_out,   cudaFuncAttributeMaxDynamicSharedMemorySize, 86016);

    k0_init<<<32, 256>>>();
    k1_fused<<<592, 256, 98304>>>(dg, xin, yin, q1w, q2w, kvw);
    k2a_dw <<<dim3(16, 192, 8), 256>>>(qdw, kvdw);
    k2b_gram<<<dim3(16, 4, 8), 256>>>();
    k4_out <<<304, 256, 86016>>>(out, pjw, temp);
}

// round 9
// speedup vs baseline: 1.1514x; 1.1514x over previous
#include <cuda_runtime.h>
#include <cuda_bf16.h>
#include <cstdint>

#define HW 65536
#define EPSN 1e-12f

typedef unsigned long long u64;

// ---------------- scratch (static device globals; no allocation) ----------------
__device__ unsigned g_qmb[16777216]; // [8][64][32768] bf16-pair qm
__device__ unsigned g_kvl[16777216]; // [8][64][32768] bf16-pair kvm low (k source)
__device__ float    g_kvh[33554432]; // [8][64][65536] f32 kvm high (v source)
__device__ float    g_v  [33554432]; // [8][64][65536] v after dwconv
__device__ unsigned g_qb [16777216]; // [8][64][32768] bf16 q_dw
__device__ unsigned g_kb [16777216]; // [8][64][32768] bf16 k_dw
__device__ float g_gram[8192];       // [8][4][16][16]
__device__ float g_qss[512];         // [8][64]
__device__ float g_kss[512];         // [8][64]

// ---------------- f32x2 helpers ----------------
__device__ __forceinline__ u64 pk2(float lo, float hi){
    u64 r; asm("mov.b64 %0, {%1, %2};" : "=l"(r) : "f"(lo), "f"(hi)); return r;
}
__device__ __forceinline__ void upk2(u64 v, float& lo, float& hi){
    asm("mov.b64 {%0, %1}, %2;" : "=f"(lo), "=f"(hi) : "l"(v));
}
__device__ __forceinline__ u64 ffma2(u64 a, u64 b, u64 c){
    u64 d; asm("fma.rn.f32x2 %0, %1, %2, %3;" : "=l"(d) : "l"(a), "l"(b), "l"(c)); return d;
}
__device__ __forceinline__ void fma_bcast(u64 (&acc)[2], float w, const u64 (&p)[2]){
    u64 wp = pk2(w, w);
    acc[0] = ffma2(wp, p[0], acc[0]);
    acc[1] = ffma2(wp, p[1], acc[1]);
}
__device__ __forceinline__ float bflo(unsigned u){ return __int_as_float((int)(u << 16)); }
__device__ __forceinline__ float bfhi(unsigned u){ return __int_as_float((int)(u & 0xffff0000u)); }
__device__ __forceinline__ unsigned pkbf(float a, float b){
    __nv_bfloat162 p = __floats2bfloat162_rn(a, b);
    return *(unsigned*)&p;
}

// ---------------- cp.async helpers ----------------
__device__ __forceinline__ void cpa16(void* smem, const void* g){
    unsigned s = (unsigned)__cvta_generic_to_shared(smem);
    asm volatile("cp.async.cg.shared.global [%0], [%1], 16;" :: "r"(s), "l"(g));
}
__device__ __forceinline__ void cpa_commit(){ asm volatile("cp.async.commit_group;"); }
__device__ __forceinline__ void cpa_wait1(){ asm volatile("cp.async.wait_group 1;"); }

// ---------------- warp mma (arch-generic bf16 HMMA) ----------------
__device__ __forceinline__ void mma16816(float* c, const unsigned* a, const unsigned* b){
    asm volatile("mma.sync.aligned.m16n8k16.row.col.f32.bf16.bf16.f32 "
        "{%0,%1,%2,%3}, {%4,%5,%6,%7}, {%8,%9}, {%0,%1,%2,%3};"
        : "+f"(c[0]), "+f"(c[1]), "+f"(c[2]), "+f"(c[3])
        : "r"(a[0]), "r"(a[1]), "r"(a[2]), "r"(a[3]), "r"(b[0]), "r"(b[1]));
}

// ---------------- K0: zero the accumulators (every replay) ----------------
__global__ void k0_init(){
    int i = blockIdx.x * 256 + threadIdx.x;
    if (i < 8192) g_gram[i] = 0.f;
    if (i < 512){ g_qss[i] = 0.f; g_kss[i] = 0.f; }
}

#define NTILES 4096   // 128-px tiles over 8 batches x 65536 px
#define ROWW 36       // bf16 smem row stride in 32-bit words (72 bf16, padded)

// ---------------- K1a: q path via mma.sync bf16 (R6 proven) ----------------
__global__ void __launch_bounds__(256, 3) k1a_mma(
    const float* __restrict__ dg, const float* __restrict__ xin,
    const float* __restrict__ q1w, const float* __restrict__ q2w)
{
    extern __shared__ unsigned smk[];
    unsigned* sD = smk;
    unsigned* sX = smk + 128*ROWW;
    const int tid = threadIdx.x, wid = tid >> 5, lane = tid & 31;
    const int mb = wid & 3, nh = wid >> 2;
    const int grow = lane >> 2, t = lane & 3;

    unsigned aW1[4][4], aW2[4][4];
    {
        const int r0 = mb*16 + grow;
        #pragma unroll
        for (int cc = 0; cc < 4; ++cc){
            const int k0 = cc*16 + t*2;
            aW1[cc][0] = pkbf(__ldg(q1w + r0*64 + k0),       __ldg(q1w + r0*64 + k0 + 1));
            aW1[cc][1] = pkbf(__ldg(q1w + (r0+8)*64 + k0),   __ldg(q1w + (r0+8)*64 + k0 + 1));
            aW1[cc][2] = pkbf(__ldg(q1w + r0*64 + k0 + 8),   __ldg(q1w + r0*64 + k0 + 9));
            aW1[cc][3] = pkbf(__ldg(q1w + (r0+8)*64 + k0+8), __ldg(q1w + (r0+8)*64 + k0 + 9));
            aW2[cc][0] = pkbf(__ldg(q2w + r0*64 + k0),       __ldg(q2w + r0*64 + k0 + 1));
            aW2[cc][1] = pkbf(__ldg(q2w + (r0+8)*64 + k0),   __ldg(q2w + (r0+8)*64 + k0 + 1));
            aW2[cc][2] = pkbf(__ldg(q2w + r0*64 + k0 + 8),   __ldg(q2w + r0*64 + k0 + 9));
            aW2[cc][3] = pkbf(__ldg(q2w + (r0+8)*64 + k0+8), __ldg(q2w + (r0+8)*64 + k0 + 9));
        }
    }

    auto cvt = [&](const float* gsrc, unsigned* sT){
        #pragma unroll
        for (int j = 0; j < 8; ++j){
            const int idx = tid + j*256;
            const int ch = idx & 63;
            const int px0 = (idx >> 6) << 2;
            float4 v = __ldg((const float4*)(gsrc + (size_t)ch*HW + px0));
            float o0 = __shfl_xor_sync(0xffffffffu, v.x, 1);
            float o1 = __shfl_xor_sync(0xffffffffu, v.y, 1);
            float o2 = __shfl_xor_sync(0xffffffffu, v.z, 1);
            float o3 = __shfl_xor_sync(0xffffffffu, v.w, 1);
            const int cp = ch >> 1;
            if (!(ch & 1)){
                sT[(px0    )*ROWW + cp] = pkbf(v.x, o0);
                sT[(px0 + 1)*ROWW + cp] = pkbf(v.y, o1);
            } else {
                sT[(px0 + 2)*ROWW + cp] = pkbf(o2, v.z);
                sT[(px0 + 3)*ROWW + cp] = pkbf(o3, v.w);
            }
        }
    };

    for (int tt = blockIdx.x; tt < NTILES; tt += gridDim.x){
        const int bb = tt >> 9;
        const size_t pxb = (size_t)(tt & 511) << 7;

        cvt(dg  + (size_t)bb*64*HW + pxb, sD);
        cvt(xin + (size_t)bb*64*HW + pxb, sX);
        __syncthreads();

        const int pxw0 = (int)(pxb >> 1);
        #pragma unroll
        for (int nt = 0; nt < 8; ++nt){
            const int nb = nh*64 + nt*8;
            const int nrow = nb + grow;
            float ac1[4] = {0.f, 0.f, 0.f, 0.f};
            float ac2[4] = {0.f, 0.f, 0.f, 0.f};
            #pragma unroll
            for (int cc = 0; cc < 4; ++cc){
                unsigned bD[2], bX[2];
                const int w0 = nrow*ROWW + cc*8 + t;
                bD[0] = sD[w0]; bD[1] = sD[w0 + 4];
                bX[0] = sX[w0]; bX[1] = sX[w0 + 4];
                mma16816(ac1, aW1[cc], bD);
                mma16816(ac2, aW2[cc], bX);
            }
            const int ch = bb*64 + mb*16 + grow;
            const int pxp = pxw0 + (nb >> 1) + t;
            g_qmb[(size_t)ch*32768 + pxp]       = pkbf(ac1[0]*ac2[0], ac1[1]*ac2[1]);
            g_qmb[(size_t)(ch + 8)*32768 + pxp] = pkbf(ac1[2]*ac2[2], ac1[3]*ac2[3]);
        }
        __syncthreads();
    }
}

// ---------------- K1b: kv GEMM (128 outs): k half -> bf16, v half -> f32 (R6 proven) ----------------
__global__ void __launch_bounds__(256, 2) k1b_kv(
    const float* __restrict__ yin, const float* __restrict__ kvw)
{
    extern __shared__ float sm[];
    float* sW  = sm;
    float* buf = sm + 8192;
    const int tid = threadIdx.x, tx = tid & 31, ty = tid >> 5;

    for (int i = tid; i < 2048; i += 256)
        *(float4*)(sW + (i<<2)) = *(const float4*)(kvw + (i<<2));

    auto issue = [&](int t, int s){
        if (t < NTILES){
            const int b = t >> 9; const size_t base = (size_t)(t & 511) << 7;
            const float* gy = yin + (size_t)b*64*HW + base;
            float* sY = buf + s*8192;
            #pragma unroll
            for (int i = tid; i < 2048; i += 256){
                const int c = i >> 5, off = (i & 31) << 2;
                cpa16(sY + c*128 + off, gy + (size_t)c*HW + off);
            }
        }
        cpa_commit();
    };

    int s = 0;
    issue(blockIdx.x, 0);
    for (int t = blockIdx.x; t < NTILES; t += gridDim.x){
        issue(t + gridDim.x, s ^ 1);
        cpa_wait1();
        __syncthreads();

        const float* sY = buf + s*8192;
        u64 av[16][2];
        #pragma unroll
        for (int i = 0; i < 16; ++i){ av[i][0]=av[i][1]=0ull; }

        #pragma unroll 4
        for (int k0 = 0; k0 < 64; k0 += 4){
            u64 yP[4][2];
            #pragma unroll
            for (int kk = 0; kk < 4; ++kk){
                float4 y4 = *(const float4*)(sY + (k0+kk)*128 + (tx<<2));
                yP[kk][0] = pk2(y4.x, y4.y); yP[kk][1] = pk2(y4.z, y4.w);
            }
            #pragma unroll
            for (int i = 0; i < 16; ++i){
                const int o = ty + (i<<3);
                float4 w = *(const float4*)(sW + o*64 + k0);
                fma_bcast(av[i], w.x, yP[0]); fma_bcast(av[i], w.y, yP[1]);
                fma_bcast(av[i], w.z, yP[2]); fma_bcast(av[i], w.w, yP[3]);
            }
        }
        const int b = t >> 9; const size_t base = (size_t)(t & 511) << 7;
        #pragma unroll
        for (int i = 0; i < 8; ++i){     // k channels -> bf16
            const int o = ty + (i<<3);
            float4 r; upk2(av[i][0], r.x, r.y); upk2(av[i][1], r.z, r.w);
            uint2 u; u.x = pkbf(r.x, r.y); u.y = pkbf(r.z, r.w);
            *(uint2*)(g_kvl + (((size_t)(b*64 + o))*HW + base + (tx<<2) >> 1)) = u;
        }
        #pragma unroll
        for (int i = 8; i < 16; ++i){    // v channels -> f32
            const int o = ty + ((i - 8)<<3);
            float4 r; upk2(av[i][0], r.x, r.y); upk2(av[i][1], r.z, r.w);
            *(float4*)(g_kvh + ((size_t)(b*64 + o))*HW + base + (tx<<2)) = r;
        }
        __syncthreads();
        s ^= 1;
    }
}

// ---------------- K2a: depthwise 3x3, one channel-plane per block ----------------
__global__ void __launch_bounds__(256) k2a_dw(
    const float* __restrict__ qdw, const float* __restrict__ kvdw)
{
    const int b = blockIdx.z, plane = blockIdx.y, band = blockIdx.x;
    const int kind = plane >> 6;           // 0=q, 1=k, 2=v
    const int c = plane & 63;

    const float* w9;
    const unsigned* srcb = nullptr; const float* srcf = nullptr;
    if (kind == 0){ srcb = g_qmb + (((size_t)(b*64 + c))*HW >> 1); w9 = qdw  + c*9; }
    else if (kind == 1){ srcb = g_kvl + (((size_t)(b*64 + c))*HW >> 1); w9 = kvdw + c*9; }
    else { srcf = g_kvh + ((size_t)(b*64 + c))*HW; w9 = kvdw + (64 + c)*9; }

    float w[9];
    #pragma unroll
    for (int i = 0; i < 9; ++i) w[i] = __ldg(w9 + i);

    const int tid = threadIdx.x;
    const int rg = tid >> 6, xq = tid & 63, xx = xq << 2;
    const int lane = tid & 31;
    const int y0 = band*16 + rg*4;

    float4 o[4];
    #pragma unroll
    for (int j = 0; j < 4; ++j) o[j] = make_float4(0.f, 0.f, 0.f, 0.f);

    #pragma unroll
    for (int i = 0; i < 6; ++i){
        const int ys = y0 - 1 + i;
        const bool yok = (ys >= 0) && (ys <= 255);
        float4 c4 = make_float4(0.f, 0.f, 0.f, 0.f);
        float lv, rv;
        if (kind == 2){
            const float* row = srcf + ys*256 + xx;
            if (yok) c4 = __ldg((const float4*)row);
            lv = __shfl_up_sync(0xffffffffu, c4.w, 1);
            rv = __shfl_down_sync(0xffffffffu, c4.x, 1);
            if (lane == 0)  lv = (yok && xx > 0)   ? __ldg(row - 1) : 0.f;
            if (lane == 31) rv = (yok && xx < 252) ? __ldg(row + 4) : 0.f;
        } else {
            const unsigned* row = srcb + (ys << 7) + (xx >> 1);
            if (yok){
                uint2 u = __ldg((const uint2*)row);
                c4.x = bflo(u.x); c4.y = bfhi(u.x); c4.z = bflo(u.y); c4.w = bfhi(u.y);
            }
            lv = __shfl_up_sync(0xffffffffu, c4.w, 1);
            rv = __shfl_down_sync(0xffffffffu, c4.x, 1);
            if (lane == 0)  lv = (yok && xx > 0)   ? bfhi(__ldg(row - 1)) : 0.f;
            if (lane == 31) rv = (yok && xx < 252) ? bflo(__ldg(row + 2)) : 0.f;
        }

        #pragma unroll
        for (int j = 0; j < 4; ++j){
            const int ky = i - j;
            if (ky >= 0 && ky < 3){
                const float wa = w[ky*3], wb = w[ky*3+1], wc = w[ky*3+2];
                o[j].x += wa*lv   + wb*c4.x + wc*c4.y;
                o[j].y += wa*c4.x + wb*c4.y + wc*c4.z;
                o[j].z += wa*c4.y + wb*c4.z + wc*c4.w;
                o[j].w += wa*c4.z + wb*c4.w + wc*rv;
            }
        }
    }

    const size_t obase = ((size_t)(b*64 + c))*HW + (size_t)y0*256 + xx;

    if (kind == 2){
        #pragma unroll
        for (int j = 0; j < 4; ++j)
            *(float4*)(g_v + obase + j*256) = o[j];
        return;
    }

    float s = 0.f;
    #pragma unroll
    for (int j = 0; j < 4; ++j)
        s += o[j].x*o[j].x + o[j].y*o[j].y + o[j].z*o[j].z + o[j].w*o[j].w;
    #pragma unroll
    for (int off = 16; off; off >>= 1) s += __shfl_xor_sync(0xffffffffu, s, off);
    if (lane == 0)
        atomicAdd((kind == 0 ? g_qss : g_kss) + b*64 + c, s);

    unsigned* dst = (kind == 0 ? g_qb : g_kb);
    #pragma unroll
    for (int j = 0; j < 4; ++j){
        uint2 u;
        u.x = pkbf(o[j].x, o[j].y);
        u.y = pkbf(o[j].z, o[j].w);
        *(uint2*)(dst + ((obase + (size_t)j*256) >> 1)) = u;
    }
}

// ---------------- K2b: gram via mma.sync (16x16 per head over pixels) ----------------
// grid (32 chunks, 4 heads, 8 batch). 8 warps; warp covers 64 words = 128 px per iter-range.
__global__ void __launch_bounds__(256) k2b_mma()
{
    __shared__ float sG[8][256];
    const int b = blockIdx.z, h = blockIdx.y, chunk = blockIdx.x;
    const int tid = threadIdx.x, wid = tid >> 5, lane = tid & 31;
    const int grow = lane >> 2, t = lane & 3;

    const unsigned* qb = g_qb + ((size_t)(b*64 + h*16)) * 32768;
    const unsigned* kb = g_kb + ((size_t)(b*64 + h*16)) * 32768;

    const int pw0 = chunk*1024 + wid*128;   // word base for this warp (128 words = 256 px)

    float c0[4] = {0.f, 0.f, 0.f, 0.f};
    float c1[4] = {0.f, 0.f, 0.f, 0.f};

    #pragma unroll 4
    for (int it = 0; it < 16; ++it){
        const int pw = pw0 + it*8;
        unsigned a[4], b0[2], b1[2];
        a[0]  = __ldg(qb + (size_t)grow*32768     + pw + t);
        a[1]  = __ldg(qb + (size_t)(grow+8)*32768 + pw + t);
        a[2]  = __ldg(qb + (size_t)grow*32768     + pw + t + 4);
        a[3]  = __ldg(qb + (size_t)(grow+8)*32768 + pw + t + 4);
        b0[0] = __ldg(kb + (size_t)grow*32768     + pw + t);
        b0[1] = __ldg(kb + (size_t)grow*32768     + pw + t + 4);
        b1[0] = __ldg(kb + (size_t)(grow+8)*32768 + pw + t);
        b1[1] = __ldg(kb + (size_t)(grow+8)*32768 + pw + t + 4);
        mma16816(c0, a, b0);
        mma16816(c1, a, b1);
    }

    // lay out C[row][col] into per-warp smem slab
    sG[wid][grow*16      + t*2    ] = c0[0];
    sG[wid][grow*16      + t*2 + 1] = c0[1];
    sG[wid][(grow+8)*16  + t*2    ] = c0[2];
    sG[wid][(grow+8)*16  + t*2 + 1] = c0[3];
    sG[wid][grow*16 + 8  + t*2    ] = c1[0];
    sG[wid][grow*16 + 8  + t*2 + 1] = c1[1];
    sG[wid][(grow+8)*16 + 8 + t*2    ] = c1[2];
    sG[wid][(grow+8)*16 + 8 + t*2 + 1] = c1[3];
    __syncthreads();

    float s = 0.f;
    #pragma unroll
    for (int w = 0; w < 8; ++w) s += sG[w][tid];
    atomicAdd(g_gram + (b*4 + h)*256 + tid, s);
}

// ---------------- K4: per-batch blocks; prologue computes M = proj∘softmax, then M@v ----------------
// smem: sV 2x8192f (65536B) | sM 4096f (16384B) | sA 1024f (4096B) = 86016B
__global__ void __launch_bounds__(256, 2) k4_out(
    float* __restrict__ out,
    const float* __restrict__ pjw, const float* __restrict__ temp)
{
    extern __shared__ float sm[];
    float* buf = sm;            // 2 stages x 8192
    float* sM  = sm + 16384;    // 4096
    float* sA  = sm + 20480;    // 1024
    const int tid = threadIdx.x, tx = tid & 31, ty = tid >> 5;
    const int b = blockIdx.x & 7;
    const int sub = blockIdx.x >> 3;
    const int bstride = gridDim.x >> 3;

    // ---- prologue: softmax attn + fold proj -> sM ----
    if (tid < 64){
        const int h = tid >> 4;
        const float t = __ldg(temp + h);
        const float inq = t / fmaxf(sqrtf(g_qss[b*64 + tid]), EPSN);
        const float* gr = g_gram + (b*4 + h)*256 + (tid & 15)*16;
        float l[16]; float mx = -1e30f;
        #pragma unroll
        for (int d = 0; d < 16; ++d){
            l[d] = gr[d] * inq / fmaxf(sqrtf(g_kss[b*64 + h*16 + d]), EPSN);
            mx = fmaxf(mx, l[d]);
        }
        float ssum = 0.f;
        #pragma unroll
        for (int d = 0; d < 16; ++d){ l[d] = __expf(l[d] - mx); ssum += l[d]; }
        const float inv = 1.f / ssum;
        #pragma unroll
        for (int d = 0; d < 16; ++d) sA[tid*16 + d] = l[d] * inv;
    }
    __syncthreads();
    for (int idx = tid; idx < 4096; idx += 256){
        const int o = idx >> 6, cd = idx & 63, h = cd >> 4, d = cd & 15;
        float s = 0.f;
        #pragma unroll
        for (int ci = 0; ci < 16; ++ci)
            s += __ldg(pjw + o*64 + h*16 + ci) * sA[(h*16 + ci)*16 + d];
        sM[idx] = s;
    }
    __syncthreads();

    // ---- main loop: 512 in-batch tiles, double-buffered sV ----
    auto issue = [&](int t, int s){
        if (t < 512){
            const size_t base = (size_t)t << 7;
            const float* gv = g_v + (size_t)b*64*HW + base;
            float* sV = buf + s*8192;
            #pragma unroll
            for (int i = tid; i < 2048; i += 256){
                const int c = i >> 5, off = (i & 31) << 2;
                cpa16(sV + c*128 + off, gv + (size_t)c*HW + off);
            }
        }
        cpa_commit();
    };

    int s = 0;
    issue(sub, 0);
    for (int t = sub; t < 512; t += bstride){
        issue(t + bstride, s ^ 1);
        cpa_wait1();
        __syncthreads();

        const float* sV = buf + s*8192;
        u64 acc[8][2];
        #pragma unroll
        for (int i = 0; i < 8; ++i){ acc[i][0] = acc[i][1] = 0ull; }

        #pragma unroll 4
        for (int k0 = 0; k0 < 64; k0 += 4){
            u64 vP[4][2];
            #pragma unroll
            for (int kk = 0; kk < 4; ++kk){
                float4 v4 = *(const float4*)(sV + (k0+kk)*128 + (tx<<2));
                vP[kk][0] = pk2(v4.x, v4.y); vP[kk][1] = pk2(v4.z, v4.w);
            }
            #pragma unroll
            for (int i = 0; i < 8; ++i){
                float4 w = *(const float4*)(sM + (ty + (i<<3))*64 + k0);
                fma_bcast(acc[i], w.x, vP[0]); fma_bcast(acc[i], w.y, vP[1]);
                fma_bcast(acc[i], w.z, vP[2]); fma_bcast(acc[i], w.w, vP[3]);
            }
        }
        const size_t base = (size_t)t << 7;
        #pragma unroll
        for (int i = 0; i < 8; ++i){
            const int o = ty + (i<<3);
            float4 r; upk2(acc[i][0], r.x, r.y); upk2(acc[i][1], r.z, r.w);
            *(float4*)(out + ((size_t)(b*64 + o))*HW + base + (tx<<2)) = r;
        }
        __syncthreads();
        s ^= 1;
    }
}

// ---------------- launch ----------------
extern "C" void kernel_launch(void* const* d_in, const int* in_sizes, int n_in,
                              void* d_out, int out_size)
{
    (void)in_sizes; (void)n_in; (void)out_size;
    const float* dg   = (const float*)d_in[0];
    const float* xin  = (const float*)d_in[1];
    const float* yin  = (const float*)d_in[2];
    const float* q1w  = (const float*)d_in[3];
    const float* q2w  = (const float*)d_in[4];
    const float* qdw  = (const float*)d_in[5];
    const float* kvw  = (const float*)d_in[6];
    const float* kvdw = (const float*)d_in[7];
    const float* pjw  = (const float*)d_in[8];
    const float* temp = (const float*)d_in[9];
    float* out = (float*)d_out;

    cudaFuncSetAttribute(k1a_mma, cudaFuncAttributeMaxDynamicSharedMemorySize, 36864);
    cudaFuncSetAttribute(k1b_kv,  cudaFuncAttributeMaxDynamicSharedMemorySize, 98304);
    cudaFuncSetAttribute(k4_out,  cudaFuncAttributeMaxDynamicSharedMemorySize, 86016);

    k0_init<<<32, 256>>>();
    k1a_mma<<<444, 256, 36864>>>(dg, xin, q1w, q2w);
    k1b_kv <<<304, 256, 98304>>>(yin, kvw);
    k2a_dw <<<dim3(16, 192, 8), 256>>>(qdw, kvdw);
    k2b_mma<<<dim3(32, 4, 8), 256>>>();
    k4_out <<<304, 256, 86016>>>(out, pjw, temp);
}

// round 10
// speedup vs baseline: 1.2857x; 1.1167x over previous
#include <cuda_runtime.h>
#include <cuda_bf16.h>
#include <cstdint>

#define HW 65536
#define EPSN 1e-12f

typedef unsigned long long u64;

// ---------------- scratch (static device globals; no allocation) ----------------
__device__ unsigned g_qmb[16777216]; // [8][64][32768] bf16-pair qm
__device__ unsigned g_kvl[16777216]; // [8][64][32768] bf16-pair kvm low (k source)
__device__ float    g_kvh[33554432]; // [8][64][65536] f32 kvm high (v source)
__device__ float    g_v  [33554432]; // [8][64][65536] v after dwconv
__device__ unsigned g_qb [16777216]; // [8][64][32768] bf16 q_dw
__device__ unsigned g_kb [16777216]; // [8][64][32768] bf16 k_dw
__device__ float g_gram[8192];       // [8][4][16][16]
__device__ float g_qss[512];         // [8][64]
__device__ float g_kss[512];         // [8][64]

// ---------------- helpers ----------------
__device__ __forceinline__ u64 pk2(float lo, float hi){
    u64 r; asm("mov.b64 %0, {%1, %2};" : "=l"(r) : "f"(lo), "f"(hi)); return r;
}
__device__ __forceinline__ void upk2(u64 v, float& lo, float& hi){
    asm("mov.b64 {%0, %1}, %2;" : "=f"(lo), "=f"(hi) : "l"(v));
}
__device__ __forceinline__ u64 ffma2(u64 a, u64 b, u64 c){
    u64 d; asm("fma.rn.f32x2 %0, %1, %2, %3;" : "=l"(d) : "l"(a), "l"(b), "l"(c)); return d;
}
__device__ __forceinline__ void fma_bcast(u64 (&acc)[2], float w, const u64 (&p)[2]){
    u64 wp = pk2(w, w);
    acc[0] = ffma2(wp, p[0], acc[0]);
    acc[1] = ffma2(wp, p[1], acc[1]);
}
__device__ __forceinline__ float bflo(unsigned u){ return __int_as_float((int)(u << 16)); }
__device__ __forceinline__ float bfhi(unsigned u){ return __int_as_float((int)(u & 0xffff0000u)); }
__device__ __forceinline__ unsigned pkbf(float a, float b){
    __nv_bfloat162 p = __floats2bfloat162_rn(a, b);
    return *(unsigned*)&p;
}
__device__ __forceinline__ float bf16f(float x){
    return __bfloat162float(__float2bfloat16_rn(x));
}

// ---------------- cp.async helpers ----------------
__device__ __forceinline__ void cpa16(void* smem, const void* g){
    unsigned s = (unsigned)__cvta_generic_to_shared(smem);
    asm volatile("cp.async.cg.shared.global [%0], [%1], 16;" :: "r"(s), "l"(g));
}
__device__ __forceinline__ void cpa_commit(){ asm volatile("cp.async.commit_group;"); }
__device__ __forceinline__ void cpa_wait1(){ asm volatile("cp.async.wait_group 1;"); }

// ---------------- warp mma (arch-generic bf16 HMMA) ----------------
__device__ __forceinline__ void mma16816(float* c, const unsigned* a, const unsigned* b){
    asm volatile("mma.sync.aligned.m16n8k16.row.col.f32.bf16.bf16.f32 "
        "{%0,%1,%2,%3}, {%4,%5,%6,%7}, {%8,%9}, {%0,%1,%2,%3};"
        : "+f"(c[0]), "+f"(c[1]), "+f"(c[2]), "+f"(c[3])
        : "r"(a[0]), "r"(a[1]), "r"(a[2]), "r"(a[3]), "r"(b[0]), "r"(b[1]));
}

// ---------------- K0: zero the accumulators (every replay) ----------------
__global__ void k0_init(){
    int i = blockIdx.x * 256 + threadIdx.x;
    if (i < 8192) g_gram[i] = 0.f;
    if (i < 512){ g_qss[i] = 0.f; g_kss[i] = 0.f; }
}

#define NTILES 4096   // 128-px tiles over 8 batches x 65536 px
#define ROWW 36       // bf16 smem row stride in 32-bit words (72 bf16, padded)

// ---------------- K1a: q path via mma.sync bf16 (R6 proven) ----------------
__global__ void __launch_bounds__(256, 3) k1a_mma(
    const float* __restrict__ dg, const float* __restrict__ xin,
    const float* __restrict__ q1w, const float* __restrict__ q2w)
{
    extern __shared__ unsigned smk[];
    unsigned* sD = smk;
    unsigned* sX = smk + 128*ROWW;
    const int tid = threadIdx.x, wid = tid >> 5, lane = tid & 31;
    const int mb = wid & 3, nh = wid >> 2;
    const int grow = lane >> 2, t = lane & 3;

    unsigned aW1[4][4], aW2[4][4];
    {
        const int r0 = mb*16 + grow;
        #pragma unroll
        for (int cc = 0; cc < 4; ++cc){
            const int k0 = cc*16 + t*2;
            aW1[cc][0] = pkbf(__ldg(q1w + r0*64 + k0),       __ldg(q1w + r0*64 + k0 + 1));
            aW1[cc][1] = pkbf(__ldg(q1w + (r0+8)*64 + k0),   __ldg(q1w + (r0+8)*64 + k0 + 1));
            aW1[cc][2] = pkbf(__ldg(q1w + r0*64 + k0 + 8),   __ldg(q1w + r0*64 + k0 + 9));
            aW1[cc][3] = pkbf(__ldg(q1w + (r0+8)*64 + k0+8), __ldg(q1w + (r0+8)*64 + k0 + 9));
            aW2[cc][0] = pkbf(__ldg(q2w + r0*64 + k0),       __ldg(q2w + r0*64 + k0 + 1));
            aW2[cc][1] = pkbf(__ldg(q2w + (r0+8)*64 + k0),   __ldg(q2w + (r0+8)*64 + k0 + 1));
            aW2[cc][2] = pkbf(__ldg(q2w + r0*64 + k0 + 8),   __ldg(q2w + r0*64 + k0 + 9));
            aW2[cc][3] = pkbf(__ldg(q2w + (r0+8)*64 + k0+8), __ldg(q2w + (r0+8)*64 + k0 + 9));
        }
    }

    auto cvt = [&](const float* gsrc, unsigned* sT){
        #pragma unroll
        for (int j = 0; j < 8; ++j){
            const int idx = tid + j*256;
            const int ch = idx & 63;
            const int px0 = (idx >> 6) << 2;
            float4 v = __ldg((const float4*)(gsrc + (size_t)ch*HW + px0));
            float o0 = __shfl_xor_sync(0xffffffffu, v.x, 1);
            float o1 = __shfl_xor_sync(0xffffffffu, v.y, 1);
            float o2 = __shfl_xor_sync(0xffffffffu, v.z, 1);
            float o3 = __shfl_xor_sync(0xffffffffu, v.w, 1);
            const int cp = ch >> 1;
            if (!(ch & 1)){
                sT[(px0    )*ROWW + cp] = pkbf(v.x, o0);
                sT[(px0 + 1)*ROWW + cp] = pkbf(v.y, o1);
            } else {
                sT[(px0 + 2)*ROWW + cp] = pkbf(o2, v.z);
                sT[(px0 + 3)*ROWW + cp] = pkbf(o3, v.w);
            }
        }
    };

    for (int tt = blockIdx.x; tt < NTILES; tt += gridDim.x){
        const int bb = tt >> 9;
        const size_t pxb = (size_t)(tt & 511) << 7;

        cvt(dg  + (size_t)bb*64*HW + pxb, sD);
        cvt(xin + (size_t)bb*64*HW + pxb, sX);
        __syncthreads();

        const int pxw0 = (int)(pxb >> 1);
        #pragma unroll
        for (int nt = 0; nt < 8; ++nt){
            const int nb = nh*64 + nt*8;
            const int nrow = nb + grow;
            float ac1[4] = {0.f, 0.f, 0.f, 0.f};
            float ac2[4] = {0.f, 0.f, 0.f, 0.f};
            #pragma unroll
            for (int cc = 0; cc < 4; ++cc){
                unsigned bD[2], bX[2];
                const int w0 = nrow*ROWW + cc*8 + t;
                bD[0] = sD[w0]; bD[1] = sD[w0 + 4];
                bX[0] = sX[w0]; bX[1] = sX[w0 + 4];
                mma16816(ac1, aW1[cc], bD);
                mma16816(ac2, aW2[cc], bX);
            }
            const int ch = bb*64 + mb*16 + grow;
            const int pxp = pxw0 + (nb >> 1) + t;
            g_qmb[(size_t)ch*32768 + pxp]       = pkbf(ac1[0]*ac2[0], ac1[1]*ac2[1]);
            g_qmb[(size_t)(ch + 8)*32768 + pxp] = pkbf(ac1[2]*ac2[2], ac1[3]*ac2[3]);
        }
        __syncthreads();
    }
}

// ---------------- K1b: kv GEMM via split-bf16 mma ----------------
// k half: Wk_bf16 @ y_hi -> bf16 pairs (g_kvl)
// v half: Wvh@yh + Wvh@yl + Wvl@yh -> f32 (g_kvh), err ~ eps^2
// smem: sYh,sYl = [128 px][36 words] each (36864B) -> 3 CTAs/SM
__global__ void __launch_bounds__(256, 3) k1b_mma(
    const float* __restrict__ yin, const float* __restrict__ kvw)
{
    extern __shared__ unsigned smk[];
    unsigned* sYh = smk;
    unsigned* sYl = smk + 128*ROWW;
    const int tid = threadIdx.x, wid = tid >> 5, lane = tid & 31;
    const int mb = wid & 3, nh = wid >> 2;
    const int grow = lane >> 2, t = lane & 3;

    unsigned aWk[4][4], aWvh[4][4], aWvl[4][4];
    {
        const int r0 = mb*16 + grow;
        #pragma unroll
        for (int cc = 0; cc < 4; ++cc){
            const int k0 = cc*16 + t*2;
            // k half (rows 0..63): plain bf16
            aWk[cc][0] = pkbf(__ldg(kvw + r0*64 + k0),       __ldg(kvw + r0*64 + k0 + 1));
            aWk[cc][1] = pkbf(__ldg(kvw + (r0+8)*64 + k0),   __ldg(kvw + (r0+8)*64 + k0 + 1));
            aWk[cc][2] = pkbf(__ldg(kvw + r0*64 + k0 + 8),   __ldg(kvw + r0*64 + k0 + 9));
            aWk[cc][3] = pkbf(__ldg(kvw + (r0+8)*64 + k0+8), __ldg(kvw + (r0+8)*64 + k0 + 9));
            // v half (rows 64..127): hi + lo split
            const float* vw = kvw + 4096;
            float w00 = __ldg(vw + r0*64 + k0),       w01 = __ldg(vw + r0*64 + k0 + 1);
            float w10 = __ldg(vw + (r0+8)*64 + k0),   w11 = __ldg(vw + (r0+8)*64 + k0 + 1);
            float w20 = __ldg(vw + r0*64 + k0 + 8),   w21 = __ldg(vw + r0*64 + k0 + 9);
            float w30 = __ldg(vw + (r0+8)*64 + k0+8), w31 = __ldg(vw + (r0+8)*64 + k0 + 9);
            aWvh[cc][0] = pkbf(w00, w01); aWvl[cc][0] = pkbf(w00 - bf16f(w00), w01 - bf16f(w01));
            aWvh[cc][1] = pkbf(w10, w11); aWvl[cc][1] = pkbf(w10 - bf16f(w10), w11 - bf16f(w11));
            aWvh[cc][2] = pkbf(w20, w21); aWvl[cc][2] = pkbf(w20 - bf16f(w20), w21 - bf16f(w21));
            aWvh[cc][3] = pkbf(w30, w31); aWvl[cc][3] = pkbf(w30 - bf16f(w30), w31 - bf16f(w31));
        }
    }

    for (int tt = blockIdx.x; tt < NTILES; tt += gridDim.x){
        const int bb = tt >> 9;
        const size_t pxb = (size_t)(tt & 511) << 7;
        const float* gy = yin + (size_t)bb*64*HW + pxb;

        // convert y -> (hi, lo) bf16 tiles
        #pragma unroll
        for (int j = 0; j < 8; ++j){
            const int idx = tid + j*256;
            const int ch = idx & 63;
            const int px0 = (idx >> 6) << 2;
            float4 v = __ldg((const float4*)(gy + (size_t)ch*HW + px0));
            float h0 = bf16f(v.x), h1 = bf16f(v.y), h2 = bf16f(v.z), h3 = bf16f(v.w);
            float l0 = v.x - h0, l1 = v.y - h1, l2 = v.z - h2, l3 = v.w - h3;
            float oh0 = __shfl_xor_sync(0xffffffffu, h0, 1);
            float oh1 = __shfl_xor_sync(0xffffffffu, h1, 1);
            float oh2 = __shfl_xor_sync(0xffffffffu, h2, 1);
            float oh3 = __shfl_xor_sync(0xffffffffu, h3, 1);
            float ol0 = __shfl_xor_sync(0xffffffffu, l0, 1);
            float ol1 = __shfl_xor_sync(0xffffffffu, l1, 1);
            float ol2 = __shfl_xor_sync(0xffffffffu, l2, 1);
            float ol3 = __shfl_xor_sync(0xffffffffu, l3, 1);
            const int cp = ch >> 1;
            if (!(ch & 1)){
                sYh[(px0    )*ROWW + cp] = pkbf(h0, oh0);
                sYh[(px0 + 1)*ROWW + cp] = pkbf(h1, oh1);
                sYl[(px0    )*ROWW + cp] = pkbf(l0, ol0);
                sYl[(px0 + 1)*ROWW + cp] = pkbf(l1, ol1);
            } else {
                sYh[(px0 + 2)*ROWW + cp] = pkbf(oh2, h2);
                sYh[(px0 + 3)*ROWW + cp] = pkbf(oh3, h3);
                sYl[(px0 + 2)*ROWW + cp] = pkbf(ol2, l2);
                sYl[(px0 + 3)*ROWW + cp] = pkbf(ol3, l3);
            }
        }
        __syncthreads();

        const int pxw0 = (int)(pxb >> 1);
        #pragma unroll
        for (int nt = 0; nt < 8; ++nt){
            const int nb = nh*64 + nt*8;
            const int nrow = nb + grow;
            float ack[4] = {0.f, 0.f, 0.f, 0.f};
            float acv[4] = {0.f, 0.f, 0.f, 0.f};
            #pragma unroll
            for (int cc = 0; cc < 4; ++cc){
                unsigned bH[2], bL[2];
                const int w0 = nrow*ROWW + cc*8 + t;
                bH[0] = sYh[w0]; bH[1] = sYh[w0 + 4];
                bL[0] = sYl[w0]; bL[1] = sYl[w0 + 4];
                mma16816(ack, aWk[cc],  bH);
                mma16816(acv, aWvh[cc], bH);
                mma16816(acv, aWvh[cc], bL);
                mma16816(acv, aWvl[cc], bH);
            }
            const int ch = bb*64 + mb*16 + grow;
            const int pxp = pxw0 + (nb >> 1) + t;
            g_kvl[(size_t)ch*32768 + pxp]       = pkbf(ack[0], ack[1]);
            g_kvl[(size_t)(ch + 8)*32768 + pxp] = pkbf(ack[2], ack[3]);
            const size_t pxa = pxb + nb + 2*t;
            float2 v01; v01.x = acv[0]; v01.y = acv[1];
            float2 v23; v23.x = acv[2]; v23.y = acv[3];
            *(float2*)(g_kvh + (size_t)ch*HW + pxa)       = v01;
            *(float2*)(g_kvh + (size_t)(ch + 8)*HW + pxa) = v23;
        }
        __syncthreads();
    }
}

// ---------------- K2a: depthwise 3x3, one channel-plane per block ----------------
__global__ void __launch_bounds__(256) k2a_dw(
    const float* __restrict__ qdw, const float* __restrict__ kvdw)
{
    const int b = blockIdx.z, plane = blockIdx.y, band = blockIdx.x;
    const int kind = plane >> 6;           // 0=q, 1=k, 2=v
    const int c = plane & 63;

    const float* w9;
    const unsigned* srcb = nullptr; const float* srcf = nullptr;
    if (kind == 0){ srcb = g_qmb + (((size_t)(b*64 + c))*HW >> 1); w9 = qdw  + c*9; }
    else if (kind == 1){ srcb = g_kvl + (((size_t)(b*64 + c))*HW >> 1); w9 = kvdw + c*9; }
    else { srcf = g_kvh + ((size_t)(b*64 + c))*HW; w9 = kvdw + (64 + c)*9; }

    float w[9];
    #pragma unroll
    for (int i = 0; i < 9; ++i) w[i] = __ldg(w9 + i);

    const int tid = threadIdx.x;
    const int rg = tid >> 6, xq = tid & 63, xx = xq << 2;
    const int lane = tid & 31;
    const int y0 = band*16 + rg*4;

    float4 o[4];
    #pragma unroll
    for (int j = 0; j < 4; ++j) o[j] = make_float4(0.f, 0.f, 0.f, 0.f);

    #pragma unroll
    for (int i = 0; i < 6; ++i){
        const int ys = y0 - 1 + i;
        const bool yok = (ys >= 0) && (ys <= 255);
        float4 c4 = make_float4(0.f, 0.f, 0.f, 0.f);
        float lv, rv;
        if (kind == 2){
            const float* row = srcf + ys*256 + xx;
            if (yok) c4 = __ldg((const float4*)row);
            lv = __shfl_up_sync(0xffffffffu, c4.w, 1);
            rv = __shfl_down_sync(0xffffffffu, c4.x, 1);
            if (lane == 0)  lv = (yok && xx > 0)   ? __ldg(row - 1) : 0.f;
            if (lane == 31) rv = (yok && xx < 252) ? __ldg(row + 4) : 0.f;
        } else {
            const unsigned* row = srcb + (ys << 7) + (xx >> 1);
            if (yok){
                uint2 u = __ldg((const uint2*)row);
                c4.x = bflo(u.x); c4.y = bfhi(u.x); c4.z = bflo(u.y); c4.w = bfhi(u.y);
            }
            lv = __shfl_up_sync(0xffffffffu, c4.w, 1);
            rv = __shfl_down_sync(0xffffffffu, c4.x, 1);
            if (lane == 0)  lv = (yok && xx > 0)   ? bfhi(__ldg(row - 1)) : 0.f;
            if (lane == 31) rv = (yok && xx < 252) ? bflo(__ldg(row + 2)) : 0.f;
        }

        #pragma unroll
        for (int j = 0; j < 4; ++j){
            const int ky = i - j;
            if (ky >= 0 && ky < 3){
                const float wa = w[ky*3], wb = w[ky*3+1], wc = w[ky*3+2];
                o[j].x += wa*lv   + wb*c4.x + wc*c4.y;
                o[j].y += wa*c4.x + wb*c4.y + wc*c4.z;
                o[j].z += wa*c4.y + wb*c4.z + wc*c4.w;
                o[j].w += wa*c4.z + wb*c4.w + wc*rv;
            }
        }
    }

    const size_t obase = ((size_t)(b*64 + c))*HW + (size_t)y0*256 + xx;

    if (kind == 2){
        #pragma unroll
        for (int j = 0; j < 4; ++j)
            *(float4*)(g_v + obase + j*256) = o[j];
        return;
    }

    float s = 0.f;
    #pragma unroll
    for (int j = 0; j < 4; ++j)
        s += o[j].x*o[j].x + o[j].y*o[j].y + o[j].z*o[j].z + o[j].w*o[j].w;
    #pragma unroll
    for (int off = 16; off; off >>= 1) s += __shfl_xor_sync(0xffffffffu, s, off);
    if (lane == 0)
        atomicAdd((kind == 0 ? g_qss : g_kss) + b*64 + c, s);

    unsigned* dst = (kind == 0 ? g_qb : g_kb);
    #pragma unroll
    for (int j = 0; j < 4; ++j){
        uint2 u;
        u.x = pkbf(o[j].x, o[j].y);
        u.y = pkbf(o[j].z, o[j].w);
        *(uint2*)(dst + ((obase + (size_t)j*256) >> 1)) = u;
    }
}

// ---------------- K2b: gram via mma.sync (R9 proven) ----------------
__global__ void __launch_bounds__(256) k2b_mma()
{
    __shared__ float sG[8][256];
    const int b = blockIdx.z, h = blockIdx.y, chunk = blockIdx.x;
    const int tid = threadIdx.x, wid = tid >> 5, lane = tid & 31;
    const int grow = lane >> 2, t = lane & 3;

    const unsigned* qb = g_qb + ((size_t)(b*64 + h*16)) * 32768;
    const unsigned* kb = g_kb + ((size_t)(b*64 + h*16)) * 32768;

    const int pw0 = chunk*1024 + wid*128;

    float c0[4] = {0.f, 0.f, 0.f, 0.f};
    float c1[4] = {0.f, 0.f, 0.f, 0.f};

    #pragma unroll 4
    for (int it = 0; it < 16; ++it){
        const int pw = pw0 + it*8;
        unsigned a[4], b0[2], b1[2];
        a[0]  = __ldg(qb + (size_t)grow*32768     + pw + t);
        a[1]  = __ldg(qb + (size_t)(grow+8)*32768 + pw + t);
        a[2]  = __ldg(qb + (size_t)grow*32768     + pw + t + 4);
        a[3]  = __ldg(qb + (size_t)(grow+8)*32768 + pw + t + 4);
        b0[0] = __ldg(kb + (size_t)grow*32768     + pw + t);
        b0[1] = __ldg(kb + (size_t)grow*32768     + pw + t + 4);
        b1[0] = __ldg(kb + (size_t)(grow+8)*32768 + pw + t);
        b1[1] = __ldg(kb + (size_t)(grow+8)*32768 + pw + t + 4);
        mma16816(c0, a, b0);
        mma16816(c1, a, b1);
    }

    sG[wid][grow*16      + t*2    ] = c0[0];
    sG[wid][grow*16      + t*2 + 1] = c0[1];
    sG[wid][(grow+8)*16  + t*2    ] = c0[2];
    sG[wid][(grow+8)*16  + t*2 + 1] = c0[3];
    sG[wid][grow*16 + 8  + t*2    ] = c1[0];
    sG[wid][grow*16 + 8  + t*2 + 1] = c1[1];
    sG[wid][(grow+8)*16 + 8 + t*2    ] = c1[2];
    sG[wid][(grow+8)*16 + 8 + t*2 + 1] = c1[3];
    __syncthreads();

    float s = 0.f;
    #pragma unroll
    for (int w = 0; w < 8; ++w) s += sG[w][tid];
    atomicAdd(g_gram + (b*4 + h)*256 + tid, s);
}

// ---------------- K4: per-batch blocks; prologue computes M = proj∘softmax, then M@v ----------------
__global__ void __launch_bounds__(256, 2) k4_out(
    float* __restrict__ out,
    const float* __restrict__ pjw, const float* __restrict__ temp)
{
    extern __shared__ float sm[];
    float* buf = sm;            // 2 stages x 8192
    float* sM  = sm + 16384;    // 4096
    float* sA  = sm + 20480;    // 1024
    const int tid = threadIdx.x, tx = tid & 31, ty = tid >> 5;
    const int b = blockIdx.x & 7;
    const int sub = blockIdx.x >> 3;
    const int bstride = gridDim.x >> 3;

    if (tid < 64){
        const int h = tid >> 4;
        const float t = __ldg(temp + h);
        const float inq = t / fmaxf(sqrtf(g_qss[b*64 + tid]), EPSN);
        const float* gr = g_gram + (b*4 + h)*256 + (tid & 15)*16;
        float l[16]; float mx = -1e30f;
        #pragma unroll
        for (int d = 0; d < 16; ++d){
            l[d] = gr[d] * inq / fmaxf(sqrtf(g_kss[b*64 + h*16 + d]), EPSN);
            mx = fmaxf(mx, l[d]);
        }
        float ssum = 0.f;
        #pragma unroll
        for (int d = 0; d < 16; ++d){ l[d] = __expf(l[d] - mx); ssum += l[d]; }
        const float inv = 1.f / ssum;
        #pragma unroll
        for (int d = 0; d < 16; ++d) sA[tid*16 + d] = l[d] * inv;
    }
    __syncthreads();
    for (int idx = tid; idx < 4096; idx += 256){
        const int o = idx >> 6, cd = idx & 63, h = cd >> 4, d = cd & 15;
        float s = 0.f;
        #pragma unroll
        for (int ci = 0; ci < 16; ++ci)
            s += __ldg(pjw + o*64 + h*16 + ci) * sA[(h*16 + ci)*16 + d];
        sM[idx] = s;
    }
    __syncthreads();

    auto issue = [&](int t, int s){
        if (t < 512){
            const size_t base = (size_t)t << 7;
            const float* gv = g_v + (size_t)b*64*HW + base;
            float* sV = buf + s*8192;
            #pragma unroll
            for (int i = tid; i < 2048; i += 256){
                const int c = i >> 5, off = (i & 31) << 2;
                cpa16(sV + c*128 + off, gv + (size_t)c*HW + off);
            }
        }
        cpa_commit();
    };

    int s = 0;
    issue(sub, 0);
    for (int t = sub; t < 512; t += bstride){
        issue(t + bstride, s ^ 1);
        cpa_wait1();
        __syncthreads();

        const float* sV = buf + s*8192;
        u64 acc[8][2];
        #pragma unroll
        for (int i = 0; i < 8; ++i){ acc[i][0] = acc[i][1] = 0ull; }

        #pragma unroll 4
        for (int k0 = 0; k0 < 64; k0 += 4){
            u64 vP[4][2];
            #pragma unroll
            for (int kk = 0; kk < 4; ++kk){
                float4 v4 = *(const float4*)(sV + (k0+kk)*128 + (tx<<2));
                vP[kk][0] = pk2(v4.x, v4.y); vP[kk][1] = pk2(v4.z, v4.w);
            }
            #pragma unroll
            for (int i = 0; i < 8; ++i){
                float4 w = *(const float4*)(sM + (ty + (i<<3))*64 + k0);
                fma_bcast(acc[i], w.x, vP[0]); fma_bcast(acc[i], w.y, vP[1]);
                fma_bcast(acc[i], w.z, vP[2]); fma_bcast(acc[i], w.w, vP[3]);
            }
        }
        const size_t base = (size_t)t << 7;
        #pragma unroll
        for (int i = 0; i < 8; ++i){
            const int o = ty + (i<<3);
            float4 r; upk2(acc[i][0], r.x, r.y); upk2(acc[i][1], r.z, r.w);
            *(float4*)(out + ((size_t)(b*64 + o))*HW + base + (tx<<2)) = r;
        }
        __syncthreads();
        s ^= 1;
    }
}

// ---------------- launch ----------------
extern "C" void kernel_launch(void* const* d_in, const int* in_sizes, int n_in,
                              void* d_out, int out_size)
{
    (void)in_sizes; (void)n_in; (void)out_size;
    const float* dg   = (const float*)d_in[0];
    const float* xin  = (const float*)d_in[1];
    const float* yin  = (const float*)d_in[2];
    const float* q1w  = (const float*)d_in[3];
    const float* q2w  = (const float*)d_in[4];
    const float* qdw  = (const float*)d_in[5];
    const float* kvw  = (const float*)d_in[6];
    const float* kvdw = (const float*)d_in[7];
    const float* pjw  = (const float*)d_in[8];
    const float* temp = (const float*)d_in[9];
    float* out = (float*)d_out;

    cudaFuncSetAttribute(k1a_mma, cudaFuncAttributeMaxDynamicSharedMemorySize, 36864);
    cudaFuncSetAttribute(k1b_mma, cudaFuncAttributeMaxDynamicSharedMemorySize, 36864);
    cudaFuncSetAttribute(k4_out,  cudaFuncAttributeMaxDynamicSharedMemorySize, 86016);

    k0_init<<<32, 256>>>();
    k1a_mma<<<444, 256, 36864>>>(dg, xin, q1w, q2w);
    k1b_mma<<<444, 256, 36864>>>(yin, kvw);
    k2a_dw <<<dim3(16, 192, 8), 256>>>(qdw, kvdw);
    k2b_mma<<<dim3(32, 4, 8), 256>>>();
    k4_out <<<304, 256, 86016>>>(out, pjw, temp);
}

// round 11
// speedup vs baseline: 1.3026x; 1.0131x over previous
#include <cuda_runtime.h>
#include <cuda_bf16.h>
#include <cstdint>

#define HW 65536
#define EPSN 1e-12f

typedef unsigned long long u64;

// ---------------- scratch (static device globals; no allocation) ----------------
__device__ unsigned g_qmb[16777216]; // [8][64][32768] bf16-pair qm
__device__ unsigned g_kvl[16777216]; // [8][64][32768] bf16-pair kvm low (k source)
__device__ float    g_kvh[33554432]; // [8][64][65536] f32 kvm high (v source)
__device__ float    g_v  [33554432]; // [8][64][65536] v after dwconv
__device__ unsigned g_qb [16777216]; // [8][64][32768] bf16 q_dw
__device__ unsigned g_kb [16777216]; // [8][64][32768] bf16 k_dw
__device__ float g_gram[8192];       // [8][4][16][16]
__device__ float g_qss[512];         // [8][64]
__device__ float g_kss[512];         // [8][64]

// ---------------- helpers ----------------
__device__ __forceinline__ float bflo(unsigned u){ return __int_as_float((int)(u << 16)); }
__device__ __forceinline__ float bfhi(unsigned u){ return __int_as_float((int)(u & 0xffff0000u)); }
__device__ __forceinline__ unsigned pkbf(float a, float b){
    __nv_bfloat162 p = __floats2bfloat162_rn(a, b);
    return *(unsigned*)&p;
}
__device__ __forceinline__ float bf16f(float x){
    return __bfloat162float(__float2bfloat16_rn(x));
}

// ---------------- warp mma (arch-generic bf16 HMMA) ----------------
__device__ __forceinline__ void mma16816(float* c, const unsigned* a, const unsigned* b){
    asm volatile("mma.sync.aligned.m16n8k16.row.col.f32.bf16.bf16.f32 "
        "{%0,%1,%2,%3}, {%4,%5,%6,%7}, {%8,%9}, {%0,%1,%2,%3};"
        : "+f"(c[0]), "+f"(c[1]), "+f"(c[2]), "+f"(c[3])
        : "r"(a[0]), "r"(a[1]), "r"(a[2]), "r"(a[3]), "r"(b[0]), "r"(b[1]));
}

// ---------------- K0: zero the accumulators (every replay) ----------------
__global__ void k0_init(){
    int i = blockIdx.x * 256 + threadIdx.x;
    if (i < 8192) g_gram[i] = 0.f;
    if (i < 512){ g_qss[i] = 0.f; g_kss[i] = 0.f; }
}

#define NTILES 4096   // 128-px tiles over 8 batches x 65536 px
#define ROWW 36       // bf16 smem row stride in 32-bit words (72 bf16, padded)

// ---------------- K1a: q path via mma.sync bf16 (R6 proven) ----------------
__global__ void __launch_bounds__(256, 3) k1a_mma(
    const float* __restrict__ dg, const float* __restrict__ xin,
    const float* __restrict__ q1w, const float* __restrict__ q2w)
{
    extern __shared__ unsigned smk[];
    unsigned* sD = smk;
    unsigned* sX = smk + 128*ROWW;
    const int tid = threadIdx.x, wid = tid >> 5, lane = tid & 31;
    const int mb = wid & 3, nh = wid >> 2;
    const int grow = lane >> 2, t = lane & 3;

    unsigned aW1[4][4], aW2[4][4];
    {
        const int r0 = mb*16 + grow;
        #pragma unroll
        for (int cc = 0; cc < 4; ++cc){
            const int k0 = cc*16 + t*2;
            aW1[cc][0] = pkbf(__ldg(q1w + r0*64 + k0),       __ldg(q1w + r0*64 + k0 + 1));
            aW1[cc][1] = pkbf(__ldg(q1w + (r0+8)*64 + k0),   __ldg(q1w + (r0+8)*64 + k0 + 1));
            aW1[cc][2] = pkbf(__ldg(q1w + r0*64 + k0 + 8),   __ldg(q1w + r0*64 + k0 + 9));
            aW1[cc][3] = pkbf(__ldg(q1w + (r0+8)*64 + k0+8), __ldg(q1w + (r0+8)*64 + k0 + 9));
            aW2[cc][0] = pkbf(__ldg(q2w + r0*64 + k0),       __ldg(q2w + r0*64 + k0 + 1));
            aW2[cc][1] = pkbf(__ldg(q2w + (r0+8)*64 + k0),   __ldg(q2w + (r0+8)*64 + k0 + 1));
            aW2[cc][2] = pkbf(__ldg(q2w + r0*64 + k0 + 8),   __ldg(q2w + r0*64 + k0 + 9));
            aW2[cc][3] = pkbf(__ldg(q2w + (r0+8)*64 + k0+8), __ldg(q2w + (r0+8)*64 + k0 + 9));
        }
    }

    auto cvt = [&](const float* gsrc, unsigned* sT){
        #pragma unroll
        for (int j = 0; j < 8; ++j){
            const int idx = tid + j*256;
            const int ch = idx & 63;
            const int px0 = (idx >> 6) << 2;
            float4 v = __ldg((const float4*)(gsrc + (size_t)ch*HW + px0));
            float o0 = __shfl_xor_sync(0xffffffffu, v.x, 1);
            float o1 = __shfl_xor_sync(0xffffffffu, v.y, 1);
            float o2 = __shfl_xor_sync(0xffffffffu, v.z, 1);
            float o3 = __shfl_xor_sync(0xffffffffu, v.w, 1);
            const int cp = ch >> 1;
            if (!(ch & 1)){
                sT[(px0    )*ROWW + cp] = pkbf(v.x, o0);
                sT[(px0 + 1)*ROWW + cp] = pkbf(v.y, o1);
            } else {
                sT[(px0 + 2)*ROWW + cp] = pkbf(o2, v.z);
                sT[(px0 + 3)*ROWW + cp] = pkbf(o3, v.w);
            }
        }
    };

    for (int tt = blockIdx.x; tt < NTILES; tt += gridDim.x){
        const int bb = tt >> 9;
        const size_t pxb = (size_t)(tt & 511) << 7;

        cvt(dg  + (size_t)bb*64*HW + pxb, sD);
        cvt(xin + (size_t)bb*64*HW + pxb, sX);
        __syncthreads();

        const int pxw0 = (int)(pxb >> 1);
        #pragma unroll
        for (int nt = 0; nt < 8; ++nt){
            const int nb = nh*64 + nt*8;
            const int nrow = nb + grow;
            float ac1[4] = {0.f, 0.f, 0.f, 0.f};
            float ac2[4] = {0.f, 0.f, 0.f, 0.f};
            #pragma unroll
            for (int cc = 0; cc < 4; ++cc){
                unsigned bD[2], bX[2];
                const int w0 = nrow*ROWW + cc*8 + t;
                bD[0] = sD[w0]; bD[1] = sD[w0 + 4];
                bX[0] = sX[w0]; bX[1] = sX[w0 + 4];
                mma16816(ac1, aW1[cc], bD);
                mma16816(ac2, aW2[cc], bX);
            }
            const int ch = bb*64 + mb*16 + grow;
            const int pxp = pxw0 + (nb >> 1) + t;
            g_qmb[(size_t)ch*32768 + pxp]       = pkbf(ac1[0]*ac2[0], ac1[1]*ac2[1]);
            g_qmb[(size_t)(ch + 8)*32768 + pxp] = pkbf(ac1[2]*ac2[2], ac1[3]*ac2[3]);
        }
        __syncthreads();
    }
}

// ---------------- K1b: kv GEMM via split-bf16 mma (R10 proven) ----------------
__global__ void __launch_bounds__(256, 3) k1b_mma(
    const float* __restrict__ yin, const float* __restrict__ kvw)
{
    extern __shared__ unsigned smk[];
    unsigned* sYh = smk;
    unsigned* sYl = smk + 128*ROWW;
    const int tid = threadIdx.x, wid = tid >> 5, lane = tid & 31;
    const int mb = wid & 3, nh = wid >> 2;
    const int grow = lane >> 2, t = lane & 3;

    unsigned aWk[4][4], aWvh[4][4], aWvl[4][4];
    {
        const int r0 = mb*16 + grow;
        #pragma unroll
        for (int cc = 0; cc < 4; ++cc){
            const int k0 = cc*16 + t*2;
            aWk[cc][0] = pkbf(__ldg(kvw + r0*64 + k0),       __ldg(kvw + r0*64 + k0 + 1));
            aWk[cc][1] = pkbf(__ldg(kvw + (r0+8)*64 + k0),   __ldg(kvw + (r0+8)*64 + k0 + 1));
            aWk[cc][2] = pkbf(__ldg(kvw + r0*64 + k0 + 8),   __ldg(kvw + r0*64 + k0 + 9));
            aWk[cc][3] = pkbf(__ldg(kvw + (r0+8)*64 + k0+8), __ldg(kvw + (r0+8)*64 + k0 + 9));
            const float* vw = kvw + 4096;
            float w00 = __ldg(vw + r0*64 + k0),       w01 = __ldg(vw + r0*64 + k0 + 1);
            float w10 = __ldg(vw + (r0+8)*64 + k0),   w11 = __ldg(vw + (r0+8)*64 + k0 + 1);
            float w20 = __ldg(vw + r0*64 + k0 + 8),   w21 = __ldg(vw + r0*64 + k0 + 9);
            float w30 = __ldg(vw + (r0+8)*64 + k0+8), w31 = __ldg(vw + (r0+8)*64 + k0 + 9);
            aWvh[cc][0] = pkbf(w00, w01); aWvl[cc][0] = pkbf(w00 - bf16f(w00), w01 - bf16f(w01));
            aWvh[cc][1] = pkbf(w10, w11); aWvl[cc][1] = pkbf(w10 - bf16f(w10), w11 - bf16f(w11));
            aWvh[cc][2] = pkbf(w20, w21); aWvl[cc][2] = pkbf(w20 - bf16f(w20), w21 - bf16f(w21));
            aWvh[cc][3] = pkbf(w30, w31); aWvl[cc][3] = pkbf(w30 - bf16f(w30), w31 - bf16f(w31));
        }
    }

    for (int tt = blockIdx.x; tt < NTILES; tt += gridDim.x){
        const int bb = tt >> 9;
        const size_t pxb = (size_t)(tt & 511) << 7;
        const float* gy = yin + (size_t)bb*64*HW + pxb;

        #pragma unroll
        for (int j = 0; j < 8; ++j){
            const int idx = tid + j*256;
            const int ch = idx & 63;
            const int px0 = (idx >> 6) << 2;
            float4 v = __ldg((const float4*)(gy + (size_t)ch*HW + px0));
            float h0 = bf16f(v.x), h1 = bf16f(v.y), h2 = bf16f(v.z), h3 = bf16f(v.w);
            float l0 = v.x - h0, l1 = v.y - h1, l2 = v.z - h2, l3 = v.w - h3;
            float oh0 = __shfl_xor_sync(0xffffffffu, h0, 1);
            float oh1 = __shfl_xor_sync(0xffffffffu, h1, 1);
            float oh2 = __shfl_xor_sync(0xffffffffu, h2, 1);
            float oh3 = __shfl_xor_sync(0xffffffffu, h3, 1);
            float ol0 = __shfl_xor_sync(0xffffffffu, l0, 1);
            float ol1 = __shfl_xor_sync(0xffffffffu, l1, 1);
            float ol2 = __shfl_xor_sync(0xffffffffu, l2, 1);
            float ol3 = __shfl_xor_sync(0xffffffffu, l3, 1);
            const int cp = ch >> 1;
            if (!(ch & 1)){
                sYh[(px0    )*ROWW + cp] = pkbf(h0, oh0);
                sYh[(px0 + 1)*ROWW + cp] = pkbf(h1, oh1);
                sYl[(px0    )*ROWW + cp] = pkbf(l0, ol0);
                sYl[(px0 + 1)*ROWW + cp] = pkbf(l1, ol1);
            } else {
                sYh[(px0 + 2)*ROWW + cp] = pkbf(oh2, h2);
                sYh[(px0 + 3)*ROWW + cp] = pkbf(oh3, h3);
                sYl[(px0 + 2)*ROWW + cp] = pkbf(ol2, l2);
                sYl[(px0 + 3)*ROWW + cp] = pkbf(ol3, l3);
            }
        }
        __syncthreads();

        const int pxw0 = (int)(pxb >> 1);
        #pragma unroll
        for (int nt = 0; nt < 8; ++nt){
            const int nb = nh*64 + nt*8;
            const int nrow = nb + grow;
            float ack[4] = {0.f, 0.f, 0.f, 0.f};
            float acv[4] = {0.f, 0.f, 0.f, 0.f};
            #pragma unroll
            for (int cc = 0; cc < 4; ++cc){
                unsigned bH[2], bL[2];
                const int w0 = nrow*ROWW + cc*8 + t;
                bH[0] = sYh[w0]; bH[1] = sYh[w0 + 4];
                bL[0] = sYl[w0]; bL[1] = sYl[w0 + 4];
                mma16816(ack, aWk[cc],  bH);
                mma16816(acv, aWvh[cc], bH);
                mma16816(acv, aWvh[cc], bL);
                mma16816(acv, aWvl[cc], bH);
            }
            const int ch = bb*64 + mb*16 + grow;
            const int pxp = pxw0 + (nb >> 1) + t;
            g_kvl[(size_t)ch*32768 + pxp]       = pkbf(ack[0], ack[1]);
            g_kvl[(size_t)(ch + 8)*32768 + pxp] = pkbf(ack[2], ack[3]);
            const size_t pxa = pxb + nb + 2*t;
            float2 v01; v01.x = acv[0]; v01.y = acv[1];
            float2 v23; v23.x = acv[2]; v23.y = acv[3];
            *(float2*)(g_kvh + (size_t)ch*HW + pxa)       = v01;
            *(float2*)(g_kvh + (size_t)(ch + 8)*HW + pxa) = v23;
        }
        __syncthreads();
    }
}

// ---------------- K2a: depthwise 3x3, 8 px/thread, warp = full row ----------------
// block = 256 thr = 8 row-groups x 32 lanes (8 px each). Block covers 32 rows.
__global__ void __launch_bounds__(256) k2a_dw(
    const float* __restrict__ qdw, const float* __restrict__ kvdw)
{
    const int b = blockIdx.z, plane = blockIdx.y, band = blockIdx.x;
    const int kind = plane >> 6;           // 0=q, 1=k, 2=v
    const int c = plane & 63;

    const float* w9;
    const unsigned* srcb = nullptr; const float* srcf = nullptr;
    if (kind == 0){ srcb = g_qmb + (((size_t)(b*64 + c))*HW >> 1); w9 = qdw  + c*9; }
    else if (kind == 1){ srcb = g_kvl + (((size_t)(b*64 + c))*HW >> 1); w9 = kvdw + c*9; }
    else { srcf = g_kvh + ((size_t)(b*64 + c))*HW; w9 = kvdw + (64 + c)*9; }

    float w[9];
    #pragma unroll
    for (int i = 0; i < 9; ++i) w[i] = __ldg(w9 + i);

    const int tid = threadIdx.x;
    const int rg = tid >> 5, lane = tid & 31;
    const int xx = lane << 3;
    const int y0 = band*32 + rg*4;

    float o[4][8];
    #pragma unroll
    for (int j = 0; j < 4; ++j)
        #pragma unroll
        for (int p = 0; p < 8; ++p) o[j][p] = 0.f;

    #pragma unroll
    for (int i = 0; i < 6; ++i){
        const int ys = y0 - 1 + i;
        const bool yok = (ys >= 0) && (ys <= 255);
        float c8[8];
        if (kind == 2){
            float4 a = make_float4(0.f,0.f,0.f,0.f), d = make_float4(0.f,0.f,0.f,0.f);
            if (yok){
                const float* row = srcf + ys*256 + xx;
                a = __ldg((const float4*)row);
                d = __ldg((const float4*)(row + 4));
            }
            c8[0]=a.x; c8[1]=a.y; c8[2]=a.z; c8[3]=a.w;
            c8[4]=d.x; c8[5]=d.y; c8[6]=d.z; c8[7]=d.w;
        } else {
            uint4 u = make_uint4(0u,0u,0u,0u);
            if (yok) u = __ldg((const uint4*)(srcb + (ys << 7) + (xx >> 1)));
            c8[0]=bflo(u.x); c8[1]=bfhi(u.x); c8[2]=bflo(u.y); c8[3]=bfhi(u.y);
            c8[4]=bflo(u.z); c8[5]=bfhi(u.z); c8[6]=bflo(u.w); c8[7]=bfhi(u.w);
        }
        float lv = __shfl_up_sync(0xffffffffu, c8[7], 1);
        float rv = __shfl_down_sync(0xffffffffu, c8[0], 1);
        if (lane == 0)  lv = 0.f;     // x = -1 out of image
        if (lane == 31) rv = 0.f;     // x = 256 out of image

        #pragma unroll
        for (int j = 0; j < 4; ++j){
            const int ky = i - j;
            if (ky >= 0 && ky < 3){
                const float wa = w[ky*3], wb = w[ky*3+1], wc = w[ky*3+2];
                o[j][0] += wa*lv + wb*c8[0] + wc*c8[1];
                #pragma unroll
                for (int p = 1; p < 7; ++p)
                    o[j][p] += wa*c8[p-1] + wb*c8[p] + wc*c8[p+1];
                o[j][7] += wa*c8[6] + wb*c8[7] + wc*rv;
            }
        }
    }

    const size_t obase = ((size_t)(b*64 + c))*HW + (size_t)y0*256 + xx;

    if (kind == 2){
        #pragma unroll
        for (int j = 0; j < 4; ++j){
            float4 a; a.x=o[j][0]; a.y=o[j][1]; a.z=o[j][2]; a.w=o[j][3];
            float4 d; d.x=o[j][4]; d.y=o[j][5]; d.z=o[j][6]; d.w=o[j][7];
            *(float4*)(g_v + obase + (size_t)j*256)     = a;
            *(float4*)(g_v + obase + (size_t)j*256 + 4) = d;
        }
        return;
    }

    float s = 0.f;
    #pragma unroll
    for (int j = 0; j < 4; ++j)
        #pragma unroll
        for (int p = 0; p < 8; ++p) s += o[j][p]*o[j][p];
    #pragma unroll
    for (int off = 16; off; off >>= 1) s += __shfl_xor_sync(0xffffffffu, s, off);
    if (lane == 0)
        atomicAdd((kind == 0 ? g_qss : g_kss) + b*64 + c, s);

    unsigned* dst = (kind == 0 ? g_qb : g_kb);
    #pragma unroll
    for (int j = 0; j < 4; ++j){
        uint4 u;
        u.x = pkbf(o[j][0], o[j][1]);
        u.y = pkbf(o[j][2], o[j][3]);
        u.z = pkbf(o[j][4], o[j][5]);
        u.w = pkbf(o[j][6], o[j][7]);
        *(uint4*)(dst + ((obase + (size_t)j*256) >> 1)) = u;
    }
}

// ---------------- K2b: gram via mma.sync (R9 proven) ----------------
__global__ void __launch_bounds__(256) k2b_mma()
{
    __shared__ float sG[8][256];
    const int b = blockIdx.z, h = blockIdx.y, chunk = blockIdx.x;
    const int tid = threadIdx.x, wid = tid >> 5, lane = tid & 31;
    const int grow = lane >> 2, t = lane & 3;

    const unsigned* qb = g_qb + ((size_t)(b*64 + h*16)) * 32768;
    const unsigned* kb = g_kb + ((size_t)(b*64 + h*16)) * 32768;

    const int pw0 = chunk*1024 + wid*128;

    float c0[4] = {0.f, 0.f, 0.f, 0.f};
    float c1[4] = {0.f, 0.f, 0.f, 0.f};

    #pragma unroll 4
    for (int it = 0; it < 16; ++it){
        const int pw = pw0 + it*8;
        unsigned a[4], b0[2], b1[2];
        a[0]  = __ldg(qb + (size_t)grow*32768     + pw + t);
        a[1]  = __ldg(qb + (size_t)(grow+8)*32768 + pw + t);
        a[2]  = __ldg(qb + (size_t)grow*32768     + pw + t + 4);
        a[3]  = __ldg(qb + (size_t)(grow+8)*32768 + pw + t + 4);
        b0[0] = __ldg(kb + (size_t)grow*32768     + pw + t);
        b0[1] = __ldg(kb + (size_t)grow*32768     + pw + t + 4);
        b1[0] = __ldg(kb + (size_t)(grow+8)*32768 + pw + t);
        b1[1] = __ldg(kb + (size_t)(grow+8)*32768 + pw + t + 4);
        mma16816(c0, a, b0);
        mma16816(c1, a, b1);
    }

    sG[wid][grow*16      + t*2    ] = c0[0];
    sG[wid][grow*16      + t*2 + 1] = c0[1];
    sG[wid][(grow+8)*16  + t*2    ] = c0[2];
    sG[wid][(grow+8)*16  + t*2 + 1] = c0[3];
    sG[wid][grow*16 + 8  + t*2    ] = c1[0];
    sG[wid][grow*16 + 8  + t*2 + 1] = c1[1];
    sG[wid][(grow+8)*16 + 8 + t*2    ] = c1[2];
    sG[wid][(grow+8)*16 + 8 + t*2 + 1] = c1[3];
    __syncthreads();

    float s = 0.f;
    #pragma unroll
    for (int w = 0; w < 8; ++w) s += sG[w][tid];
    atomicAdd(g_gram + (b*4 + h)*256 + tid, s);
}

// ---------------- K4: split-bf16 mma; prologue computes M = proj∘softmax ----------------
// smem: sVh/sVl [128px][36w] (36864B) | sM 4096f (16384B) | sA 1024f (4096B) = 57344B
__global__ void __launch_bounds__(256, 3) k4_mma(
    float* __restrict__ out,
    const float* __restrict__ pjw, const float* __restrict__ temp)
{
    extern __shared__ unsigned smk[];
    unsigned* sVh = smk;
    unsigned* sVl = smk + 128*ROWW;
    float* sM = (float*)(smk + 2*128*ROWW);   // 4096 floats
    float* sA = sM + 4096;                     // 1024 floats
    const int tid = threadIdx.x, wid = tid >> 5, lane = tid & 31;
    const int mb = wid & 3, nh = wid >> 2;
    const int grow = lane >> 2, t = lane & 3;
    const int b = blockIdx.x & 7;
    const int sub = blockIdx.x >> 3;
    const int bstride = gridDim.x >> 3;

    // ---- prologue: softmax attn + fold proj -> sM ----
    if (tid < 64){
        const int h = tid >> 4;
        const float tv = __ldg(temp + h);
        const float inq = tv / fmaxf(sqrtf(g_qss[b*64 + tid]), EPSN);
        const float* gr = g_gram + (b*4 + h)*256 + (tid & 15)*16;
        float l[16]; float mx = -1e30f;
        #pragma unroll
        for (int d = 0; d < 16; ++d){
            l[d] = gr[d] * inq / fmaxf(sqrtf(g_kss[b*64 + h*16 + d]), EPSN);
            mx = fmaxf(mx, l[d]);
        }
        float ssum = 0.f;
        #pragma unroll
        for (int d = 0; d < 16; ++d){ l[d] = __expf(l[d] - mx); ssum += l[d]; }
        const float inv = 1.f / ssum;
        #pragma unroll
        for (int d = 0; d < 16; ++d) sA[tid*16 + d] = l[d] * inv;
    }
    __syncthreads();
    for (int idx = tid; idx < 4096; idx += 256){
        const int o = idx >> 6, cd = idx & 63, h = cd >> 4, d = cd & 15;
        float s = 0.f;
        #pragma unroll
        for (int ci = 0; ci < 16; ++ci)
            s += __ldg(pjw + o*64 + h*16 + ci) * sA[(h*16 + ci)*16 + d];
        sM[idx] = s;
    }
    __syncthreads();

    // ---- build hi/lo A fragments of M from smem ----
    unsigned aMh[4][4], aMl[4][4];
    {
        const int r0 = mb*16 + grow;
        #pragma unroll
        for (int cc = 0; cc < 4; ++cc){
            const int k0 = cc*16 + t*2;
            float w00 = sM[r0*64 + k0],       w01 = sM[r0*64 + k0 + 1];
            float w10 = sM[(r0+8)*64 + k0],   w11 = sM[(r0+8)*64 + k0 + 1];
            float w20 = sM[r0*64 + k0 + 8],   w21 = sM[r0*64 + k0 + 9];
            float w30 = sM[(r0+8)*64 + k0+8], w31 = sM[(r0+8)*64 + k0 + 9];
            aMh[cc][0] = pkbf(w00, w01); aMl[cc][0] = pkbf(w00 - bf16f(w00), w01 - bf16f(w01));
            aMh[cc][1] = pkbf(w10, w11); aMl[cc][1] = pkbf(w10 - bf16f(w10), w11 - bf16f(w11));
            aMh[cc][2] = pkbf(w20, w21); aMl[cc][2] = pkbf(w20 - bf16f(w20), w21 - bf16f(w21));
            aMh[cc][3] = pkbf(w30, w31); aMl[cc][3] = pkbf(w30 - bf16f(w30), w31 - bf16f(w31));
        }
    }

    // ---- main loop: 512 in-batch 128-px tiles ----
    for (int tt = sub; tt < 512; tt += bstride){
        const size_t pxb = (size_t)tt << 7;
        const float* gv = g_v + (size_t)b*64*HW + pxb;

        #pragma unroll
        for (int j = 0; j < 8; ++j){
            const int idx = tid + j*256;
            const int ch = idx & 63;
            const int px0 = (idx >> 6) << 2;
            float4 v = __ldg((const float4*)(gv + (size_t)ch*HW + px0));
            float h0 = bf16f(v.x), h1 = bf16f(v.y), h2 = bf16f(v.z), h3 = bf16f(v.w);
            float l0 = v.x - h0, l1 = v.y - h1, l2 = v.z - h2, l3 = v.w - h3;
            float oh0 = __shfl_xor_sync(0xffffffffu, h0, 1);
            float oh1 = __shfl_xor_sync(0xffffffffu, h1, 1);
            float oh2 = __shfl_xor_sync(0xffffffffu, h2, 1);
            float oh3 = __shfl_xor_sync(0xffffffffu, h3, 1);
            float ol0 = __shfl_xor_sync(0xffffffffu, l0, 1);
            float ol1 = __shfl_xor_sync(0xffffffffu, l1, 1);
            float ol2 = __shfl_xor_sync(0xffffffffu, l2, 1);
            float ol3 = __shfl_xor_sync(0xffffffffu, l3, 1);
            const int cp = ch >> 1;
            if (!(ch & 1)){
                sVh[(px0    )*ROWW + cp] = pkbf(h0, oh0);
                sVh[(px0 + 1)*ROWW + cp] = pkbf(h1, oh1);
                sVl[(px0    )*ROWW + cp] = pkbf(l0, ol0);
                sVl[(px0 + 1)*ROWW + cp] = pkbf(l1, ol1);
            } else {
                sVh[(px0 + 2)*ROWW + cp] = pkbf(oh2, h2);
                sVh[(px0 + 3)*ROWW + cp] = pkbf(oh3, h3);
                sVl[(px0 + 2)*ROWW + cp] = pkbf(ol2, l2);
                sVl[(px0 + 3)*ROWW + cp] = pkbf(ol3, l3);
            }
        }
        __syncthreads();

        #pragma unroll
        for (int nt = 0; nt < 8; ++nt){
            const int nb = nh*64 + nt*8;
            const int nrow = nb + grow;
            float acv[4] = {0.f, 0.f, 0.f, 0.f};
            #pragma unroll
            for (int cc = 0; cc < 4; ++cc){
                unsigned bH[2], bL[2];
                const int w0 = nrow*ROWW + cc*8 + t;
                bH[0] = sVh[w0]; bH[1] = sVh[w0 + 4];
                bL[0] = sVl[w0]; bL[1] = sVl[w0 + 4];
                mma16816(acv, aMh[cc], bH);
                mma16816(acv, aMh[cc], bL);
                mma16816(acv, aMl[cc], bH);
            }
            const int ch = b*64 + mb*16 + grow;
            const size_t pxa = pxb + nb + 2*t;
            float2 v01; v01.x = acv[0]; v01.y = acv[1];
            float2 v23; v23.x = acv[2]; v23.y = acv[3];
            *(float2*)(out + (size_t)ch*HW + pxa)       = v01;
            *(float2*)(out + (size_t)(ch + 8)*HW + pxa) = v23;
        }
        __syncthreads();
    }
}

// ---------------- launch ----------------
extern "C" void kernel_launch(void* const* d_in, const int* in_sizes, int n_in,
                              void* d_out, int out_size)
{
    (void)in_sizes; (void)n_in; (void)out_size;
    const float* dg   = (const float*)d_in[0];
    const float* xin  = (const float*)d_in[1];
    const float* yin  = (const float*)d_in[2];
    const float* q1w  = (const float*)d_in[3];
    const float* q2w  = (const float*)d_in[4];
    const float* qdw  = (const float*)d_in[5];
    const float* kvw  = (const float*)d_in[6];
    const float* kvdw = (const float*)d_in[7];
    const float* pjw  = (const float*)d_in[8];
    const float* temp = (const float*)d_in[9];
    float* out = (float*)d_out;

    cudaFuncSetAttribute(k1a_mma, cudaFuncAttributeMaxDynamicSharedMemorySize, 36864);
    cudaFuncSetAttribute(k1b_mma, cudaFuncAttributeMaxDynamicSharedMemorySize, 36864);
    cudaFuncSetAttribute(k4_mma,  cudaFuncAttributeMaxDynamicSharedMemorySize, 57344);

    k0_init<<<32, 256>>>();
    k1a_mma<<<444, 256, 36864>>>(dg, xin, q1w, q2w);
    k1b_mma<<<444, 256, 36864>>>(yin, kvw);
    k2a_dw <<<dim3(8, 192, 8), 256>>>(qdw, kvdw);
    k2b_mma<<<dim3(32, 4, 8), 256>>>();
    k4_mma <<<440, 256, 57344>>>(out, pjw, temp);
}

// round 12
// speedup vs baseline: 1.3340x; 1.0241x over previous
#include <cuda_runtime.h>
#include <cuda_bf16.h>
#include <cstdint>

#define HW 65536
#define EPSN 1e-12f

typedef unsigned long long u64;

// ---------------- scratch (static device globals; no allocation) ----------------
__device__ unsigned g_qmb[16777216]; // [8][64][32768] bf16-pair qm
__device__ unsigned g_kvl[16777216]; // [8][64][32768] bf16-pair kvm low (k source)
__device__ float    g_kvh[33554432]; // [8][64][65536] f32 kvm high (v source)
__device__ float    g_v  [33554432]; // [8][64][65536] v after dwconv
__device__ unsigned g_qb [16777216]; // [8][64][32768] bf16 q_dw
__device__ unsigned g_kb [16777216]; // [8][64][32768] bf16 k_dw
__device__ float g_gram[8192];       // [8][4][16][16]
__device__ float g_qss[512];         // [8][64]
__device__ float g_kss[512];         // [8][64]

// ---------------- helpers ----------------
__device__ __forceinline__ float bflo(unsigned u){ return __int_as_float((int)(u << 16)); }
__device__ __forceinline__ float bfhi(unsigned u){ return __int_as_float((int)(u & 0xffff0000u)); }
__device__ __forceinline__ unsigned pkbf(float a, float b){
    __nv_bfloat162 p = __floats2bfloat162_rn(a, b);
    return *(unsigned*)&p;
}
__device__ __forceinline__ float bf16f(float x){
    return __bfloat162float(__float2bfloat16_rn(x));
}

// ---------------- warp mma (arch-generic bf16 HMMA) ----------------
__device__ __forceinline__ void mma16816(float* c, const unsigned* a, const unsigned* b){
    asm volatile("mma.sync.aligned.m16n8k16.row.col.f32.bf16.bf16.f32 "
        "{%0,%1,%2,%3}, {%4,%5,%6,%7}, {%8,%9}, {%0,%1,%2,%3};"
        : "+f"(c[0]), "+f"(c[1]), "+f"(c[2]), "+f"(c[3])
        : "r"(a[0]), "r"(a[1]), "r"(a[2]), "r"(a[3]), "r"(b[0]), "r"(b[1]));
}

// ---------------- K0: zero the accumulators (every replay) ----------------
__global__ void k0_init(){
    int i = blockIdx.x * 256 + threadIdx.x;
    if (i < 8192) g_gram[i] = 0.f;
    if (i < 512){ g_qss[i] = 0.f; g_kss[i] = 0.f; }
}

#define NTILES 4096   // 128-px tiles over 8 batches x 65536 px
#define ROWW 36       // bf16 smem row stride in 32-bit words (72 bf16, padded)

// ---------------- K1a: q path via mma.sync bf16 (R6 proven) ----------------
__global__ void __launch_bounds__(256, 3) k1a_mma(
    const float* __restrict__ dg, const float* __restrict__ xin,
    const float* __restrict__ q1w, const float* __restrict__ q2w)
{
    extern __shared__ unsigned smk[];
    unsigned* sD = smk;
    unsigned* sX = smk + 128*ROWW;
    const int tid = threadIdx.x, wid = tid >> 5, lane = tid & 31;
    const int mb = wid & 3, nh = wid >> 2;
    const int grow = lane >> 2, t = lane & 3;

    unsigned aW1[4][4], aW2[4][4];
    {
        const int r0 = mb*16 + grow;
        #pragma unroll
        for (int cc = 0; cc < 4; ++cc){
            const int k0 = cc*16 + t*2;
            aW1[cc][0] = pkbf(__ldg(q1w + r0*64 + k0),       __ldg(q1w + r0*64 + k0 + 1));
            aW1[cc][1] = pkbf(__ldg(q1w + (r0+8)*64 + k0),   __ldg(q1w + (r0+8)*64 + k0 + 1));
            aW1[cc][2] = pkbf(__ldg(q1w + r0*64 + k0 + 8),   __ldg(q1w + r0*64 + k0 + 9));
            aW1[cc][3] = pkbf(__ldg(q1w + (r0+8)*64 + k0+8), __ldg(q1w + (r0+8)*64 + k0 + 9));
            aW2[cc][0] = pkbf(__ldg(q2w + r0*64 + k0),       __ldg(q2w + r0*64 + k0 + 1));
            aW2[cc][1] = pkbf(__ldg(q2w + (r0+8)*64 + k0),   __ldg(q2w + (r0+8)*64 + k0 + 1));
            aW2[cc][2] = pkbf(__ldg(q2w + r0*64 + k0 + 8),   __ldg(q2w + r0*64 + k0 + 9));
            aW2[cc][3] = pkbf(__ldg(q2w + (r0+8)*64 + k0+8), __ldg(q2w + (r0+8)*64 + k0 + 9));
        }
    }

    auto cvt = [&](const float* gsrc, unsigned* sT){
        #pragma unroll
        for (int j = 0; j < 8; ++j){
            const int idx = tid + j*256;
            const int ch = idx & 63;
            const int px0 = (idx >> 6) << 2;
            float4 v = __ldg((const float4*)(gsrc + (size_t)ch*HW + px0));
            float o0 = __shfl_xor_sync(0xffffffffu, v.x, 1);
            float o1 = __shfl_xor_sync(0xffffffffu, v.y, 1);
            float o2 = __shfl_xor_sync(0xffffffffu, v.z, 1);
            float o3 = __shfl_xor_sync(0xffffffffu, v.w, 1);
            const int cp = ch >> 1;
            if (!(ch & 1)){
                sT[(px0    )*ROWW + cp] = pkbf(v.x, o0);
                sT[(px0 + 1)*ROWW + cp] = pkbf(v.y, o1);
            } else {
                sT[(px0 + 2)*ROWW + cp] = pkbf(o2, v.z);
                sT[(px0 + 3)*ROWW + cp] = pkbf(o3, v.w);
            }
        }
    };

    for (int tt = blockIdx.x; tt < NTILES; tt += gridDim.x){
        const int bb = tt >> 9;
        const size_t pxb = (size_t)(tt & 511) << 7;

        cvt(dg  + (size_t)bb*64*HW + pxb, sD);
        cvt(xin + (size_t)bb*64*HW + pxb, sX);
        __syncthreads();

        const int pxw0 = (int)(pxb >> 1);
        #pragma unroll
        for (int nt = 0; nt < 8; ++nt){
            const int nb = nh*64 + nt*8;
            const int nrow = nb + grow;
            float ac1[4] = {0.f, 0.f, 0.f, 0.f};
            float ac2[4] = {0.f, 0.f, 0.f, 0.f};
            #pragma unroll
            for (int cc = 0; cc < 4; ++cc){
                unsigned bD[2], bX[2];
                const int w0 = nrow*ROWW + cc*8 + t;
                bD[0] = sD[w0]; bD[1] = sD[w0 + 4];
                bX[0] = sX[w0]; bX[1] = sX[w0 + 4];
                mma16816(ac1, aW1[cc], bD);
                mma16816(ac2, aW2[cc], bX);
            }
            const int ch = bb*64 + mb*16 + grow;
            const int pxp = pxw0 + (nb >> 1) + t;
            g_qmb[(size_t)ch*32768 + pxp]       = pkbf(ac1[0]*ac2[0], ac1[1]*ac2[1]);
            g_qmb[(size_t)(ch + 8)*32768 + pxp] = pkbf(ac1[2]*ac2[2], ac1[3]*ac2[3]);
        }
        __syncthreads();
    }
}

// ---------------- K1b: kv GEMM via split-bf16 mma (R10 proven; cvt uses 4 shfl) ----------------
__global__ void __launch_bounds__(256, 3) k1b_mma(
    const float* __restrict__ yin, const float* __restrict__ kvw)
{
    extern __shared__ unsigned smk[];
    unsigned* sYh = smk;
    unsigned* sYl = smk + 128*ROWW;
    const int tid = threadIdx.x, wid = tid >> 5, lane = tid & 31;
    const int mb = wid & 3, nh = wid >> 2;
    const int grow = lane >> 2, t = lane & 3;

    unsigned aWk[4][4], aWvh[4][4], aWvl[4][4];
    {
        const int r0 = mb*16 + grow;
        #pragma unroll
        for (int cc = 0; cc < 4; ++cc){
            const int k0 = cc*16 + t*2;
            aWk[cc][0] = pkbf(__ldg(kvw + r0*64 + k0),       __ldg(kvw + r0*64 + k0 + 1));
            aWk[cc][1] = pkbf(__ldg(kvw + (r0+8)*64 + k0),   __ldg(kvw + (r0+8)*64 + k0 + 1));
            aWk[cc][2] = pkbf(__ldg(kvw + r0*64 + k0 + 8),   __ldg(kvw + r0*64 + k0 + 9));
            aWk[cc][3] = pkbf(__ldg(kvw + (r0+8)*64 + k0+8), __ldg(kvw + (r0+8)*64 + k0 + 9));
            const float* vw = kvw + 4096;
            float w00 = __ldg(vw + r0*64 + k0),       w01 = __ldg(vw + r0*64 + k0 + 1);
            float w10 = __ldg(vw + (r0+8)*64 + k0),   w11 = __ldg(vw + (r0+8)*64 + k0 + 1);
            float w20 = __ldg(vw + r0*64 + k0 + 8),   w21 = __ldg(vw + r0*64 + k0 + 9);
            float w30 = __ldg(vw + (r0+8)*64 + k0+8), w31 = __ldg(vw + (r0+8)*64 + k0 + 9);
            aWvh[cc][0] = pkbf(w00, w01); aWvl[cc][0] = pkbf(w00 - bf16f(w00), w01 - bf16f(w01));
            aWvh[cc][1] = pkbf(w10, w11); aWvl[cc][1] = pkbf(w10 - bf16f(w10), w11 - bf16f(w11));
            aWvh[cc][2] = pkbf(w20, w21); aWvl[cc][2] = pkbf(w20 - bf16f(w20), w21 - bf16f(w21));
            aWvh[cc][3] = pkbf(w30, w31); aWvl[cc][3] = pkbf(w30 - bf16f(w30), w31 - bf16f(w31));
        }
    }

    for (int tt = blockIdx.x; tt < NTILES; tt += gridDim.x){
        const int bb = tt >> 9;
        const size_t pxb = (size_t)(tt & 511) << 7;
        const float* gy = yin + (size_t)bb*64*HW + pxb;

        #pragma unroll
        for (int j = 0; j < 8; ++j){
            const int idx = tid + j*256;
            const int ch = idx & 63;
            const int px0 = (idx >> 6) << 2;
            float4 v = __ldg((const float4*)(gy + (size_t)ch*HW + px0));
            // shuffle RAW partner values (4 shfl), derive partner hi/lo locally
            float o0 = __shfl_xor_sync(0xffffffffu, v.x, 1);
            float o1 = __shfl_xor_sync(0xffffffffu, v.y, 1);
            float o2 = __shfl_xor_sync(0xffffffffu, v.z, 1);
            float o3 = __shfl_xor_sync(0xffffffffu, v.w, 1);
            const int cp = ch >> 1;
            if (!(ch & 1)){
                float h0 = bf16f(v.x), h1 = bf16f(v.y);
                float p0 = bf16f(o0),  p1 = bf16f(o1);
                sYh[(px0    )*ROWW + cp] = pkbf(h0, p0);
                sYh[(px0 + 1)*ROWW + cp] = pkbf(h1, p1);
                sYl[(px0    )*ROWW + cp] = pkbf(v.x - h0, o0 - p0);
                sYl[(px0 + 1)*ROWW + cp] = pkbf(v.y - h1, o1 - p1);
            } else {
                float h2 = bf16f(v.z), h3 = bf16f(v.w);
                float p2 = bf16f(o2),  p3 = bf16f(o3);
                sYh[(px0 + 2)*ROWW + cp] = pkbf(p2, h2);
                sYh[(px0 + 3)*ROWW + cp] = pkbf(p3, h3);
                sYl[(px0 + 2)*ROWW + cp] = pkbf(o2 - p2, v.z - h2);
                sYl[(px0 + 3)*ROWW + cp] = pkbf(o3 - p3, v.w - h3);
            }
        }
        __syncthreads();

        const int pxw0 = (int)(pxb >> 1);
        #pragma unroll
        for (int nt = 0; nt < 8; ++nt){
            const int nb = nh*64 + nt*8;
            const int nrow = nb + grow;
            float ack[4] = {0.f, 0.f, 0.f, 0.f};
            float acv[4] = {0.f, 0.f, 0.f, 0.f};
            #pragma unroll
            for (int cc = 0; cc < 4; ++cc){
                unsigned bH[2], bL[2];
                const int w0 = nrow*ROWW + cc*8 + t;
                bH[0] = sYh[w0]; bH[1] = sYh[w0 + 4];
                bL[0] = sYl[w0]; bL[1] = sYl[w0 + 4];
                mma16816(ack, aWk[cc],  bH);
                mma16816(acv, aWvh[cc], bH);
                mma16816(acv, aWvh[cc], bL);
                mma16816(acv, aWvl[cc], bH);
            }
            const int ch = bb*64 + mb*16 + grow;
            const int pxp = pxw0 + (nb >> 1) + t;
            g_kvl[(size_t)ch*32768 + pxp]       = pkbf(ack[0], ack[1]);
            g_kvl[(size_t)(ch + 8)*32768 + pxp] = pkbf(ack[2], ack[3]);
            const size_t pxa = pxb + nb + 2*t;
            float2 v01; v01.x = acv[0]; v01.y = acv[1];
            float2 v23; v23.x = acv[2]; v23.y = acv[3];
            *(float2*)(g_kvh + (size_t)ch*HW + pxa)       = v01;
            *(float2*)(g_kvh + (size_t)(ch + 8)*HW + pxa) = v23;
        }
        __syncthreads();
    }
}

// ---------------- K2a: depthwise 3x3, 8 px/thread, warp = full row ----------------
__global__ void __launch_bounds__(256, 5) k2a_dw(
    const float* __restrict__ qdw, const float* __restrict__ kvdw)
{
    const int b = blockIdx.z, plane = blockIdx.y, band = blockIdx.x;
    const int kind = plane >> 6;           // 0=q, 1=k, 2=v
    const int c = plane & 63;

    const float* w9;
    const unsigned* srcb = nullptr; const float* srcf = nullptr;
    if (kind == 0){ srcb = g_qmb + (((size_t)(b*64 + c))*HW >> 1); w9 = qdw  + c*9; }
    else if (kind == 1){ srcb = g_kvl + (((size_t)(b*64 + c))*HW >> 1); w9 = kvdw + c*9; }
    else { srcf = g_kvh + ((size_t)(b*64 + c))*HW; w9 = kvdw + (64 + c)*9; }

    float w[9];
    #pragma unroll
    for (int i = 0; i < 9; ++i) w[i] = __ldg(w9 + i);

    const int tid = threadIdx.x;
    const int rg = tid >> 5, lane = tid & 31;
    const int xx = lane << 3;
    const int y0 = band*32 + rg*4;

    float o[4][8];
    #pragma unroll
    for (int j = 0; j < 4; ++j)
        #pragma unroll
        for (int p = 0; p < 8; ++p) o[j][p] = 0.f;

    #pragma unroll
    for (int i = 0; i < 6; ++i){
        const int ys = y0 - 1 + i;
        const bool yok = (ys >= 0) && (ys <= 255);
        float c8[8];
        if (kind == 2){
            float4 a = make_float4(0.f,0.f,0.f,0.f), d = make_float4(0.f,0.f,0.f,0.f);
            if (yok){
                const float* row = srcf + ys*256 + xx;
                a = __ldg((const float4*)row);
                d = __ldg((const float4*)(row + 4));
            }
            c8[0]=a.x; c8[1]=a.y; c8[2]=a.z; c8[3]=a.w;
            c8[4]=d.x; c8[5]=d.y; c8[6]=d.z; c8[7]=d.w;
        } else {
            uint4 u = make_uint4(0u,0u,0u,0u);
            if (yok) u = __ldg((const uint4*)(srcb + (ys << 7) + (xx >> 1)));
            c8[0]=bflo(u.x); c8[1]=bfhi(u.x); c8[2]=bflo(u.y); c8[3]=bfhi(u.y);
            c8[4]=bflo(u.z); c8[5]=bfhi(u.z); c8[6]=bflo(u.w); c8[7]=bfhi(u.w);
        }
        float lv = __shfl_up_sync(0xffffffffu, c8[7], 1);
        float rv = __shfl_down_sync(0xffffffffu, c8[0], 1);
        if (lane == 0)  lv = 0.f;
        if (lane == 31) rv = 0.f;

        #pragma unroll
        for (int j = 0; j < 4; ++j){
            const int ky = i - j;
            if (ky >= 0 && ky < 3){
                const float wa = w[ky*3], wb = w[ky*3+1], wc = w[ky*3+2];
                o[j][0] += wa*lv + wb*c8[0] + wc*c8[1];
                #pragma unroll
                for (int p = 1; p < 7; ++p)
                    o[j][p] += wa*c8[p-1] + wb*c8[p] + wc*c8[p+1];
                o[j][7] += wa*c8[6] + wb*c8[7] + wc*rv;
            }
        }
    }

    const size_t obase = ((size_t)(b*64 + c))*HW + (size_t)y0*256 + xx;

    if (kind == 2){
        #pragma unroll
        for (int j = 0; j < 4; ++j){
            float4 a; a.x=o[j][0]; a.y=o[j][1]; a.z=o[j][2]; a.w=o[j][3];
            float4 d; d.x=o[j][4]; d.y=o[j][5]; d.z=o[j][6]; d.w=o[j][7];
            *(float4*)(g_v + obase + (size_t)j*256)     = a;
            *(float4*)(g_v + obase + (size_t)j*256 + 4) = d;
        }
        return;
    }

    float s = 0.f;
    #pragma unroll
    for (int j = 0; j < 4; ++j)
        #pragma unroll
        for (int p = 0; p < 8; ++p) s += o[j][p]*o[j][p];
    #pragma unroll
    for (int off = 16; off; off >>= 1) s += __shfl_xor_sync(0xffffffffu, s, off);
    if (lane == 0)
        atomicAdd((kind == 0 ? g_qss : g_kss) + b*64 + c, s);

    unsigned* dst = (kind == 0 ? g_qb : g_kb);
    #pragma unroll
    for (int j = 0; j < 4; ++j){
        uint4 u;
        u.x = pkbf(o[j][0], o[j][1]);
        u.y = pkbf(o[j][2], o[j][3]);
        u.z = pkbf(o[j][4], o[j][5]);
        u.w = pkbf(o[j][6], o[j][7]);
        *(uint4*)(dst + ((obase + (size_t)j*256) >> 1)) = u;
    }
}

// ---------------- K2b: gram via mma.sync (R9 proven) ----------------
__global__ void __launch_bounds__(256) k2b_mma()
{
    __shared__ float sG[8][256];
    const int b = blockIdx.z, h = blockIdx.y, chunk = blockIdx.x;
    const int tid = threadIdx.x, wid = tid >> 5, lane = tid & 31;
    const int grow = lane >> 2, t = lane & 3;

    const unsigned* qb = g_qb + ((size_t)(b*64 + h*16)) * 32768;
    const unsigned* kb = g_kb + ((size_t)(b*64 + h*16)) * 32768;

    const int pw0 = chunk*1024 + wid*128;

    float c0[4] = {0.f, 0.f, 0.f, 0.f};
    float c1[4] = {0.f, 0.f, 0.f, 0.f};

    #pragma unroll 4
    for (int it = 0; it < 16; ++it){
        const int pw = pw0 + it*8;
        unsigned a[4], b0[2], b1[2];
        a[0]  = __ldg(qb + (size_t)grow*32768     + pw + t);
        a[1]  = __ldg(qb + (size_t)(grow+8)*32768 + pw + t);
        a[2]  = __ldg(qb + (size_t)grow*32768     + pw + t + 4);
        a[3]  = __ldg(qb + (size_t)(grow+8)*32768 + pw + t + 4);
        b0[0] = __ldg(kb + (size_t)grow*32768     + pw + t);
        b0[1] = __ldg(kb + (size_t)grow*32768     + pw + t + 4);
        b1[0] = __ldg(kb + (size_t)(grow+8)*32768 + pw + t);
        b1[1] = __ldg(kb + (size_t)(grow+8)*32768 + pw + t + 4);
        mma16816(c0, a, b0);
        mma16816(c1, a, b1);
    }

    sG[wid][grow*16      + t*2    ] = c0[0];
    sG[wid][grow*16      + t*2 + 1] = c0[1];
    sG[wid][(grow+8)*16  + t*2    ] = c0[2];
    sG[wid][(grow+8)*16  + t*2 + 1] = c0[3];
    sG[wid][grow*16 + 8  + t*2    ] = c1[0];
    sG[wid][grow*16 + 8  + t*2 + 1] = c1[1];
    sG[wid][(grow+8)*16 + 8 + t*2    ] = c1[2];
    sG[wid][(grow+8)*16 + 8 + t*2 + 1] = c1[3];
    __syncthreads();

    float s = 0.f;
    #pragma unroll
    for (int w = 0; w < 8; ++w) s += sG[w][tid];
    atomicAdd(g_gram + (b*4 + h)*256 + tid, s);
}

// ---------------- K4: split-bf16 mma; prologue computes M = proj∘softmax ----------------
__global__ void __launch_bounds__(256, 3) k4_mma(
    float* __restrict__ out,
    const float* __restrict__ pjw, const float* __restrict__ temp)
{
    extern __shared__ unsigned smk[];
    unsigned* sVh = smk;
    unsigned* sVl = smk + 128*ROWW;
    float* sM = (float*)(smk + 2*128*ROWW);   // 4096 floats
    float* sA = sM + 4096;                     // 1024 floats
    const int tid = threadIdx.x, wid = tid >> 5, lane = tid & 31;
    const int mb = wid & 3, nh = wid >> 2;
    const int grow = lane >> 2, t = lane & 3;
    const int b = blockIdx.x & 7;
    const int sub = blockIdx.x >> 3;
    const int bstride = gridDim.x >> 3;

    if (tid < 64){
        const int h = tid >> 4;
        const float tv = __ldg(temp + h);
        const float inq = tv / fmaxf(sqrtf(g_qss[b*64 + tid]), EPSN);
        const float* gr = g_gram + (b*4 + h)*256 + (tid & 15)*16;
        float l[16]; float mx = -1e30f;
        #pragma unroll
        for (int d = 0; d < 16; ++d){
            l[d] = gr[d] * inq / fmaxf(sqrtf(g_kss[b*64 + h*16 + d]), EPSN);
            mx = fmaxf(mx, l[d]);
        }
        float ssum = 0.f;
        #pragma unroll
        for (int d = 0; d < 16; ++d){ l[d] = __expf(l[d] - mx); ssum += l[d]; }
        const float inv = 1.f / ssum;
        #pragma unroll
        for (int d = 0; d < 16; ++d) sA[tid*16 + d] = l[d] * inv;
    }
    __syncthreads();
    for (int idx = tid; idx < 4096; idx += 256){
        const int o = idx >> 6, cd = idx & 63, h = cd >> 4, d = cd & 15;
        float s = 0.f;
        #pragma unroll
        for (int ci = 0; ci < 16; ++ci)
            s += __ldg(pjw + o*64 + h*16 + ci) * sA[(h*16 + ci)*16 + d];
        sM[idx] = s;
    }
    __syncthreads();

    unsigned aMh[4][4], aMl[4][4];
    {
        const int r0 = mb*16 + grow;
        #pragma unroll
        for (int cc = 0; cc < 4; ++cc){
            const int k0 = cc*16 + t*2;
            float w00 = sM[r0*64 + k0],       w01 = sM[r0*64 + k0 + 1];
            float w10 = sM[(r0+8)*64 + k0],   w11 = sM[(r0+8)*64 + k0 + 1];
            float w20 = sM[r0*64 + k0 + 8],   w21 = sM[r0*64 + k0 + 9];
            float w30 = sM[(r0+8)*64 + k0+8], w31 = sM[(r0+8)*64 + k0 + 9];
            aMh[cc][0] = pkbf(w00, w01); aMl[cc][0] = pkbf(w00 - bf16f(w00), w01 - bf16f(w01));
            aMh[cc][1] = pkbf(w10, w11); aMl[cc][1] = pkbf(w10 - bf16f(w10), w11 - bf16f(w11));
            aMh[cc][2] = pkbf(w20, w21); aMl[cc][2] = pkbf(w20 - bf16f(w20), w21 - bf16f(w21));
            aMh[cc][3] = pkbf(w30, w31); aMl[cc][3] = pkbf(w30 - bf16f(w30), w31 - bf16f(w31));
        }
    }

    for (int tt = sub; tt < 512; tt += bstride){
        const size_t pxb = (size_t)tt << 7;
        const float* gv = g_v + (size_t)b*64*HW + pxb;

        #pragma unroll
        for (int j = 0; j < 8; ++j){
            const int idx = tid + j*256;
            const int ch = idx & 63;
            const int px0 = (idx >> 6) << 2;
            float4 v = __ldg((const float4*)(gv + (size_t)ch*HW + px0));
            float o0 = __shfl_xor_sync(0xffffffffu, v.x, 1);
            float o1 = __shfl_xor_sync(0xffffffffu, v.y, 1);
            float o2 = __shfl_xor_sync(0xffffffffu, v.z, 1);
            float o3 = __shfl_xor_sync(0xffffffffu, v.w, 1);
            const int cp = ch >> 1;
            if (!(ch & 1)){
                float h0 = bf16f(v.x), h1 = bf16f(v.y);
                float p0 = bf16f(o0),  p1 = bf16f(o1);
                sVh[(px0    )*ROWW + cp] = pkbf(h0, p0);
                sVh[(px0 + 1)*ROWW + cp] = pkbf(h1, p1);
                sVl[(px0    )*ROWW + cp] = pkbf(v.x - h0, o0 - p0);
                sVl[(px0 + 1)*ROWW + cp] = pkbf(v.y - h1, o1 - p1);
            } else {
                float h2 = bf16f(v.z), h3 = bf16f(v.w);
                float p2 = bf16f(o2),  p3 = bf16f(o3);
                sVh[(px0 + 2)*ROWW + cp] = pkbf(p2, h2);
                sVh[(px0 + 3)*ROWW + cp] = pkbf(p3, h3);
                sVl[(px0 + 2)*ROWW + cp] = pkbf(o2 - p2, v.z - h2);
                sVl[(px0 + 3)*ROWW + cp] = pkbf(o3 - p3, v.w - h3);
            }
        }
        __syncthreads();

        #pragma unroll
        for (int nt = 0; nt < 8; ++nt){
            const int nb = nh*64 + nt*8;
            const int nrow = nb + grow;
            float acv[4] = {0.f, 0.f, 0.f, 0.f};
            #pragma unroll
            for (int cc = 0; cc < 4; ++cc){
                unsigned bH[2], bL[2];
                const int w0 = nrow*ROWW + cc*8 + t;
                bH[0] = sVh[w0]; bH[1] = sVh[w0 + 4];
                bL[0] = sVl[w0]; bL[1] = sVl[w0 + 4];
                mma16816(acv, aMh[cc], bH);
                mma16816(acv, aMh[cc], bL);
                mma16816(acv, aMl[cc], bH);
            }
            const int ch = b*64 + mb*16 + grow;
            const size_t pxa = pxb + nb + 2*t;
            float2 v01; v01.x = acv[0]; v01.y = acv[1];
            float2 v23; v23.x = acv[2]; v23.y = acv[3];
            *(float2*)(out + (size_t)ch*HW + pxa)       = v01;
            *(float2*)(out + (size_t)(ch + 8)*HW + pxa) = v23;
        }
        __syncthreads();
    }
}

// ---------------- launch ----------------
extern "C" void kernel_launch(void* const* d_in, const int* in_sizes, int n_in,
                              void* d_out, int out_size)
{
    (void)in_sizes; (void)n_in; (void)out_size;
    const float* dg   = (const float*)d_in[0];
    const float* xin  = (const float*)d_in[1];
    const float* yin  = (const float*)d_in[2];
    const float* q1w  = (const float*)d_in[3];
    const float* q2w  = (const float*)d_in[4];
    const float* qdw  = (const float*)d_in[5];
    const float* kvw  = (const float*)d_in[6];
    const float* kvdw = (const float*)d_in[7];
    const float* pjw  = (const float*)d_in[8];
    const float* temp = (const float*)d_in[9];
    float* out = (float*)d_out;

    cudaFuncSetAttribute(k1a_mma, cudaFuncAttributeMaxDynamicSharedMemorySize, 36864);
    cudaFuncSetAttribute(k1b_mma, cudaFuncAttributeMaxDynamicSharedMemorySize, 36864);
    cudaFuncSetAttribute(k4_mma,  cudaFuncAttributeMaxDynamicSharedMemorySize, 57344);

    k0_init<<<32, 256>>>();
    k1a_mma<<<444, 256, 36864>>>(dg, xin, q1w, q2w);
    k1b_mma<<<444, 256, 36864>>>(yin, kvw);
    k2a_dw <<<dim3(8, 192, 8), 256>>>(qdw, kvdw);
    k2b_mma<<<dim3(32, 4, 8), 256>>>();
    k4_mma <<<440, 256, 57344>>>(out, pjw, temp);
}

// round 13
// speedup vs baseline: 1.4378x; 1.0778x over previous
#include <cuda_runtime.h>
#include <cuda_bf16.h>
#include <cstdint>

#define HW 65536
#define EPSN 1e-12f

typedef unsigned long long u64;

// ---------------- scratch (static device globals; no allocation) ----------------
__device__ unsigned g_qmb[16777216]; // [8][64][32768] bf16-pair qm
__device__ unsigned g_kvl[16777216]; // [8][64][32768] bf16-pair kvm low (k source)
__device__ float    g_kvh[33554432]; // [8][64][65536] f32 kvm high (v source)
__device__ float    g_v  [33554432]; // [8][64][65536] v after dwconv
__device__ float g_gram[8192];       // [8][4][16][16]
__device__ float g_qss[512];         // [8][64]
__device__ float g_kss[512];         // [8][64]

// ---------------- helpers ----------------
__device__ __forceinline__ float bflo(unsigned u){ return __int_as_float((int)(u << 16)); }
__device__ __forceinline__ float bfhi(unsigned u){ return __int_as_float((int)(u & 0xffff0000u)); }
__device__ __forceinline__ unsigned pkbf(float a, float b){
    __nv_bfloat162 p = __floats2bfloat162_rn(a, b);
    return *(unsigned*)&p;
}
__device__ __forceinline__ float bf16f(float x){
    return __bfloat162float(__float2bfloat16_rn(x));
}

// ---------------- warp mma (arch-generic bf16 HMMA) ----------------
__device__ __forceinline__ void mma16816(float* c, const unsigned* a, const unsigned* b){
    asm volatile("mma.sync.aligned.m16n8k16.row.col.f32.bf16.bf16.f32 "
        "{%0,%1,%2,%3}, {%4,%5,%6,%7}, {%8,%9}, {%0,%1,%2,%3};"
        : "+f"(c[0]), "+f"(c[1]), "+f"(c[2]), "+f"(c[3])
        : "r"(a[0]), "r"(a[1]), "r"(a[2]), "r"(a[3]), "r"(b[0]), "r"(b[1]));
}

// ---------------- K0: zero the accumulators (every replay) ----------------
__global__ void k0_init(){
    int i = blockIdx.x * 256 + threadIdx.x;
    if (i < 8192) g_gram[i] = 0.f;
    if (i < 512){ g_qss[i] = 0.f; g_kss[i] = 0.f; }
}

#define NTILES 4096   // 128-px tiles over 8 batches x 65536 px
#define ROWW 36       // bf16 smem row stride in 32-bit words (72 bf16, padded)
#define QROW 516      // k2qk smem channel-row stride in words (512 + 4 pad)

// ---------------- K1a: q path via mma.sync bf16 (R6 proven) ----------------
__global__ void __launch_bounds__(256, 3) k1a_mma(
    const float* __restrict__ dg, const float* __restrict__ xin,
    const float* __restrict__ q1w, const float* __restrict__ q2w)
{
    extern __shared__ unsigned smk[];
    unsigned* sD = smk;
    unsigned* sX = smk + 128*ROWW;
    const int tid = threadIdx.x, wid = tid >> 5, lane = tid & 31;
    const int mb = wid & 3, nh = wid >> 2;
    const int grow = lane >> 2, t = lane & 3;

    unsigned aW1[4][4], aW2[4][4];
    {
        const int r0 = mb*16 + grow;
        #pragma unroll
        for (int cc = 0; cc < 4; ++cc){
            const int k0 = cc*16 + t*2;
            aW1[cc][0] = pkbf(__ldg(q1w + r0*64 + k0),       __ldg(q1w + r0*64 + k0 + 1));
            aW1[cc][1] = pkbf(__ldg(q1w + (r0+8)*64 + k0),   __ldg(q1w + (r0+8)*64 + k0 + 1));
            aW1[cc][2] = pkbf(__ldg(q1w + r0*64 + k0 + 8),   __ldg(q1w + r0*64 + k0 + 9));
            aW1[cc][3] = pkbf(__ldg(q1w + (r0+8)*64 + k0+8), __ldg(q1w + (r0+8)*64 + k0 + 9));
            aW2[cc][0] = pkbf(__ldg(q2w + r0*64 + k0),       __ldg(q2w + r0*64 + k0 + 1));
            aW2[cc][1] = pkbf(__ldg(q2w + (r0+8)*64 + k0),   __ldg(q2w + (r0+8)*64 + k0 + 1));
            aW2[cc][2] = pkbf(__ldg(q2w + r0*64 + k0 + 8),   __ldg(q2w + r0*64 + k0 + 9));
            aW2[cc][3] = pkbf(__ldg(q2w + (r0+8)*64 + k0+8), __ldg(q2w + (r0+8)*64 + k0 + 9));
        }
    }

    auto cvt = [&](const float* gsrc, unsigned* sT){
        #pragma unroll
        for (int j = 0; j < 8; ++j){
            const int idx = tid + j*256;
            const int ch = idx & 63;
            const int px0 = (idx >> 6) << 2;
            float4 v = __ldg((const float4*)(gsrc + (size_t)ch*HW + px0));
            float o0 = __shfl_xor_sync(0xffffffffu, v.x, 1);
            float o1 = __shfl_xor_sync(0xffffffffu, v.y, 1);
            float o2 = __shfl_xor_sync(0xffffffffu, v.z, 1);
            float o3 = __shfl_xor_sync(0xffffffffu, v.w, 1);
            const int cp = ch >> 1;
            if (!(ch & 1)){
                sT[(px0    )*ROWW + cp] = pkbf(v.x, o0);
                sT[(px0 + 1)*ROWW + cp] = pkbf(v.y, o1);
            } else {
                sT[(px0 + 2)*ROWW + cp] = pkbf(o2, v.z);
                sT[(px0 + 3)*ROWW + cp] = pkbf(o3, v.w);
            }
        }
    };

    for (int tt = blockIdx.x; tt < NTILES; tt += gridDim.x){
        const int bb = tt >> 9;
        const size_t pxb = (size_t)(tt & 511) << 7;

        cvt(dg  + (size_t)bb*64*HW + pxb, sD);
        cvt(xin + (size_t)bb*64*HW + pxb, sX);
        __syncthreads();

        const int pxw0 = (int)(pxb >> 1);
        #pragma unroll
        for (int nt = 0; nt < 8; ++nt){
            const int nb = nh*64 + nt*8;
            const int nrow = nb + grow;
            float ac1[4] = {0.f, 0.f, 0.f, 0.f};
            float ac2[4] = {0.f, 0.f, 0.f, 0.f};
            #pragma unroll
            for (int cc = 0; cc < 4; ++cc){
                unsigned bD[2], bX[2];
                const int w0 = nrow*ROWW + cc*8 + t;
                bD[0] = sD[w0]; bD[1] = sD[w0 + 4];
                bX[0] = sX[w0]; bX[1] = sX[w0 + 4];
                mma16816(ac1, aW1[cc], bD);
                mma16816(ac2, aW2[cc], bX);
            }
            const int ch = bb*64 + mb*16 + grow;
            const int pxp = pxw0 + (nb >> 1) + t;
            g_qmb[(size_t)ch*32768 + pxp]       = pkbf(ac1[0]*ac2[0], ac1[1]*ac2[1]);
            g_qmb[(size_t)(ch + 8)*32768 + pxp] = pkbf(ac1[2]*ac2[2], ac1[3]*ac2[3]);
        }
        __syncthreads();
    }
}

// ---------------- K1b: kv GEMM via split-bf16 mma (R10/R12 proven) ----------------
__global__ void __launch_bounds__(256, 3) k1b_mma(
    const float* __restrict__ yin, const float* __restrict__ kvw)
{
    extern __shared__ unsigned smk[];
    unsigned* sYh = smk;
    unsigned* sYl = smk + 128*ROWW;
    const int tid = threadIdx.x, wid = tid >> 5, lane = tid & 31;
    const int mb = wid & 3, nh = wid >> 2;
    const int grow = lane >> 2, t = lane & 3;

    unsigned aWk[4][4], aWvh[4][4], aWvl[4][4];
    {
        const int r0 = mb*16 + grow;
        #pragma unroll
        for (int cc = 0; cc < 4; ++cc){
            const int k0 = cc*16 + t*2;
            aWk[cc][0] = pkbf(__ldg(kvw + r0*64 + k0),       __ldg(kvw + r0*64 + k0 + 1));
            aWk[cc][1] = pkbf(__ldg(kvw + (r0+8)*64 + k0),   __ldg(kvw + (r0+8)*64 + k0 + 1));
            aWk[cc][2] = pkbf(__ldg(kvw + r0*64 + k0 + 8),   __ldg(kvw + r0*64 + k0 + 9));
            aWk[cc][3] = pkbf(__ldg(kvw + (r0+8)*64 + k0+8), __ldg(kvw + (r0+8)*64 + k0 + 9));
            const float* vw = kvw + 4096;
            float w00 = __ldg(vw + r0*64 + k0),       w01 = __ldg(vw + r0*64 + k0 + 1);
            float w10 = __ldg(vw + (r0+8)*64 + k0),   w11 = __ldg(vw + (r0+8)*64 + k0 + 1);
            float w20 = __ldg(vw + r0*64 + k0 + 8),   w21 = __ldg(vw + r0*64 + k0 + 9);
            float w30 = __ldg(vw + (r0+8)*64 + k0+8), w31 = __ldg(vw + (r0+8)*64 + k0 + 9);
            aWvh[cc][0] = pkbf(w00, w01); aWvl[cc][0] = pkbf(w00 - bf16f(w00), w01 - bf16f(w01));
            aWvh[cc][1] = pkbf(w10, w11); aWvl[cc][1] = pkbf(w10 - bf16f(w10), w11 - bf16f(w11));
            aWvh[cc][2] = pkbf(w20, w21); aWvl[cc][2] = pkbf(w20 - bf16f(w20), w21 - bf16f(w21));
            aWvh[cc][3] = pkbf(w30, w31); aWvl[cc][3] = pkbf(w30 - bf16f(w30), w31 - bf16f(w31));
        }
    }

    for (int tt = blockIdx.x; tt < NTILES; tt += gridDim.x){
        const int bb = tt >> 9;
        const size_t pxb = (size_t)(tt & 511) << 7;
        const float* gy = yin + (size_t)bb*64*HW + pxb;

        #pragma unroll
        for (int j = 0; j < 8; ++j){
            const int idx = tid + j*256;
            const int ch = idx & 63;
            const int px0 = (idx >> 6) << 2;
            float4 v = __ldg((const float4*)(gy + (size_t)ch*HW + px0));
            float o0 = __shfl_xor_sync(0xffffffffu, v.x, 1);
            float o1 = __shfl_xor_sync(0xffffffffu, v.y, 1);
            float o2 = __shfl_xor_sync(0xffffffffu, v.z, 1);
            float o3 = __shfl_xor_sync(0xffffffffu, v.w, 1);
            const int cp = ch >> 1;
            if (!(ch & 1)){
                float h0 = bf16f(v.x), h1 = bf16f(v.y);
                float p0 = bf16f(o0),  p1 = bf16f(o1);
                sYh[(px0    )*ROWW + cp] = pkbf(h0, p0);
                sYh[(px0 + 1)*ROWW + cp] = pkbf(h1, p1);
                sYl[(px0    )*ROWW + cp] = pkbf(v.x - h0, o0 - p0);
                sYl[(px0 + 1)*ROWW + cp] = pkbf(v.y - h1, o1 - p1);
            } else {
                float h2 = bf16f(v.z), h3 = bf16f(v.w);
                float p2 = bf16f(o2),  p3 = bf16f(o3);
                sYh[(px0 + 2)*ROWW + cp] = pkbf(p2, h2);
                sYh[(px0 + 3)*ROWW + cp] = pkbf(p3, h3);
                sYl[(px0 + 2)*ROWW + cp] = pkbf(o2 - p2, v.z - h2);
                sYl[(px0 + 3)*ROWW + cp] = pkbf(o3 - p3, v.w - h3);
            }
        }
        __syncthreads();

        const int pxw0 = (int)(pxb >> 1);
        #pragma unroll
        for (int nt = 0; nt < 8; ++nt){
            const int nb = nh*64 + nt*8;
            const int nrow = nb + grow;
            float ack[4] = {0.f, 0.f, 0.f, 0.f};
            float acv[4] = {0.f, 0.f, 0.f, 0.f};
            #pragma unroll
            for (int cc = 0; cc < 4; ++cc){
                unsigned bH[2], bL[2];
                const int w0 = nrow*ROWW + cc*8 + t;
                bH[0] = sYh[w0]; bH[1] = sYh[w0 + 4];
                bL[0] = sYl[w0]; bL[1] = sYl[w0 + 4];
                mma16816(ack, aWk[cc],  bH);
                mma16816(acv, aWvh[cc], bH);
                mma16816(acv, aWvh[cc], bL);
                mma16816(acv, aWvl[cc], bH);
            }
            const int ch = bb*64 + mb*16 + grow;
            const int pxp = pxw0 + (nb >> 1) + t;
            g_kvl[(size_t)ch*32768 + pxp]       = pkbf(ack[0], ack[1]);
            g_kvl[(size_t)(ch + 8)*32768 + pxp] = pkbf(ack[2], ack[3]);
            const size_t pxa = pxb + nb + 2*t;
            float2 v01; v01.x = acv[0]; v01.y = acv[1];
            float2 v23; v23.x = acv[2]; v23.y = acv[3];
            *(float2*)(g_kvh + (size_t)ch*HW + pxa)       = v01;
            *(float2*)(g_kvh + (size_t)(ch + 8)*HW + pxa) = v23;
        }
        __syncthreads();
    }
}

// ---------------- K2v: depthwise 3x3 for v planes only (R12 k2a, kind==2 path) ----------------
__global__ void __launch_bounds__(256, 5) k2v_dw(const float* __restrict__ kvdw)
{
    const int b = blockIdx.z, c = blockIdx.y, band = blockIdx.x;
    const float* srcf = g_kvh + ((size_t)(b*64 + c))*HW;
    const float* w9 = kvdw + (64 + c)*9;

    float w[9];
    #pragma unroll
    for (int i = 0; i < 9; ++i) w[i] = __ldg(w9 + i);

    const int tid = threadIdx.x;
    const int rg = tid >> 5, lane = tid & 31;
    const int xx = lane << 3;
    const int y0 = band*32 + rg*4;

    float o[4][8];
    #pragma unroll
    for (int j = 0; j < 4; ++j)
        #pragma unroll
        for (int p = 0; p < 8; ++p) o[j][p] = 0.f;

    #pragma unroll
    for (int i = 0; i < 6; ++i){
        const int ys = y0 - 1 + i;
        const bool yok = (ys >= 0) && (ys <= 255);
        float c8[8];
        float4 a = make_float4(0.f,0.f,0.f,0.f), d = make_float4(0.f,0.f,0.f,0.f);
        if (yok){
            const float* row = srcf + ys*256 + xx;
            a = __ldg((const float4*)row);
            d = __ldg((const float4*)(row + 4));
        }
        c8[0]=a.x; c8[1]=a.y; c8[2]=a.z; c8[3]=a.w;
        c8[4]=d.x; c8[5]=d.y; c8[6]=d.z; c8[7]=d.w;
        float lv = __shfl_up_sync(0xffffffffu, c8[7], 1);
        float rv = __shfl_down_sync(0xffffffffu, c8[0], 1);
        if (lane == 0)  lv = 0.f;
        if (lane == 31) rv = 0.f;

        #pragma unroll
        for (int j = 0; j < 4; ++j){
            const int ky = i - j;
            if (ky >= 0 && ky < 3){
                const float wa = w[ky*3], wb = w[ky*3+1], wc = w[ky*3+2];
                o[j][0] += wa*lv + wb*c8[0] + wc*c8[1];
                #pragma unroll
                for (int p = 1; p < 7; ++p)
                    o[j][p] += wa*c8[p-1] + wb*c8[p] + wc*c8[p+1];
                o[j][7] += wa*c8[6] + wb*c8[7] + wc*rv;
            }
        }
    }

    const size_t obase = ((size_t)(b*64 + c))*HW + (size_t)y0*256 + xx;
    #pragma unroll
    for (int j = 0; j < 4; ++j){
        float4 a; a.x=o[j][0]; a.y=o[j][1]; a.z=o[j][2]; a.w=o[j][3];
        float4 d; d.x=o[j][4]; d.y=o[j][5]; d.z=o[j][6]; d.w=o[j][7];
        *(float4*)(g_v + obase + (size_t)j*256)     = a;
        *(float4*)(g_v + obase + (size_t)j*256 + 4) = d;
    }
}

// ---------------- K2qk: fused q/k dwconv + gram mma (no gmem staging) ----------------
// block = (4-row band, head, batch). 8 warps x 4 jobs = 32 (ch,kind) planes.
// smem: sQ/sK [16ch][QROW words] + sG [8][256] floats = 74240 B (3 CTAs/SM).
__global__ void __launch_bounds__(256) k2qk(
    const float* __restrict__ qdw, const float* __restrict__ kvdw)
{
    extern __shared__ unsigned smq[];
    unsigned* sQ = smq;                     // 16*QROW words
    unsigned* sK = smq + 16*QROW;           // 16*QROW words
    float* sG = (float*)(smq + 32*QROW);    // 2048 floats

    const int band = blockIdx.x, h = blockIdx.y, b = blockIdx.z;
    const int tid = threadIdx.x, wid = tid >> 5, lane = tid & 31;
    const int y0 = band*4;
    const int xx = lane << 3;

    #pragma unroll
    for (int jj = 0; jj < 4; ++jj){
        const int job = wid*4 + jj;        // 0..31
        const int kindk = job & 1;         // 0=q, 1=k
        const int c = job >> 1;            // 0..15
        const int cc = h*16 + c;
        const unsigned* srcb = (kindk ? g_kvl : g_qmb) + (((size_t)(b*64 + cc))*HW >> 1);
        const float* w9 = (kindk ? kvdw : qdw) + cc*9;
        float w[9];
        #pragma unroll
        for (int i = 0; i < 9; ++i) w[i] = __ldg(w9 + i);

        float o[4][8];
        #pragma unroll
        for (int j = 0; j < 4; ++j)
            #pragma unroll
            for (int p = 0; p < 8; ++p) o[j][p] = 0.f;

        #pragma unroll
        for (int i = 0; i < 6; ++i){
            const int ys = y0 - 1 + i;
            const bool yok = (ys >= 0) && (ys <= 255);
            uint4 u = make_uint4(0u,0u,0u,0u);
            if (yok) u = __ldg((const uint4*)(srcb + (ys << 7) + (xx >> 1)));
            float c8[8];
            c8[0]=bflo(u.x); c8[1]=bfhi(u.x); c8[2]=bflo(u.y); c8[3]=bfhi(u.y);
            c8[4]=bflo(u.z); c8[5]=bfhi(u.z); c8[6]=bflo(u.w); c8[7]=bfhi(u.w);
            float lv = __shfl_up_sync(0xffffffffu, c8[7], 1);
            float rv = __shfl_down_sync(0xffffffffu, c8[0], 1);
            if (lane == 0)  lv = 0.f;
            if (lane == 31) rv = 0.f;

            #pragma unroll
            for (int j = 0; j < 4; ++j){
                const int ky = i - j;
                if (ky >= 0 && ky < 3){
                    const float wa = w[ky*3], wb = w[ky*3+1], wc = w[ky*3+2];
                    o[j][0] += wa*lv + wb*c8[0] + wc*c8[1];
                    #pragma unroll
                    for (int p = 1; p < 7; ++p)
                        o[j][p] += wa*c8[p-1] + wb*c8[p] + wc*c8[p+1];
                    o[j][7] += wa*c8[6] + wb*c8[7] + wc*rv;
                }
            }
        }

        float s = 0.f;
        #pragma unroll
        for (int j = 0; j < 4; ++j)
            #pragma unroll
            for (int p = 0; p < 8; ++p) s += o[j][p]*o[j][p];
        #pragma unroll
        for (int off = 16; off; off >>= 1) s += __shfl_xor_sync(0xffffffffu, s, off);
        if (lane == 0)
            atomicAdd((kindk ? g_kss : g_qss) + b*64 + cc, s);

        unsigned* dst = (kindk ? sK : sQ) + c*QROW;
        #pragma unroll
        for (int j = 0; j < 4; ++j){
            uint4 u;
            u.x = pkbf(o[j][0], o[j][1]);
            u.y = pkbf(o[j][2], o[j][3]);
            u.z = pkbf(o[j][4], o[j][5]);
            u.w = pkbf(o[j][6], o[j][7]);
            *(uint4*)(dst + j*128 + lane*4) = u;
        }
    }
    __syncthreads();

    // ---- gram mma over this band's 1024 px; warp covers 128 px ----
    const int grow = lane >> 2, t = lane & 3;
    float c0[4] = {0.f, 0.f, 0.f, 0.f};
    float c1[4] = {0.f, 0.f, 0.f, 0.f};

    #pragma unroll
    for (int it = 0; it < 8; ++it){
        const int wb = wid*64 + it*8;
        unsigned a[4], b0[2], b1[2];
        a[0]  = sQ[grow*QROW      + wb + t];
        a[1]  = sQ[(grow+8)*QROW  + wb + t];
        a[2]  = sQ[grow*QROW      + wb + t + 4];
        a[3]  = sQ[(grow+8)*QROW  + wb + t + 4];
        b0[0] = sK[grow*QROW      + wb + t];
        b0[1] = sK[grow*QROW      + wb + t + 4];
        b1[0] = sK[(grow+8)*QROW  + wb + t];
        b1[1] = sK[(grow+8)*QROW  + wb + t + 4];
        mma16816(c0, a, b0);
        mma16816(c1, a, b1);
    }

    sG[wid*256 + grow*16          + t*2    ] = c0[0];
    sG[wid*256 + grow*16          + t*2 + 1] = c0[1];
    sG[wid*256 + (grow+8)*16      + t*2    ] = c0[2];
    sG[wid*256 + (grow+8)*16      + t*2 + 1] = c0[3];
    sG[wid*256 + grow*16 + 8      + t*2    ] = c1[0];
    sG[wid*256 + grow*16 + 8      + t*2 + 1] = c1[1];
    sG[wid*256 + (grow+8)*16 + 8  + t*2    ] = c1[2];
    sG[wid*256 + (grow+8)*16 + 8  + t*2 + 1] = c1[3];
    __syncthreads();

    float s = 0.f;
    #pragma unroll
    for (int w = 0; w < 8; ++w) s += sG[w*256 + tid];
    atomicAdd(g_gram + (b*4 + h)*256 + tid, s);
}

// ---------------- K4: split-bf16 mma; prologue computes M = proj∘softmax (R11/R12 proven) ----------------
__global__ void __launch_bounds__(256, 3) k4_mma(
    float* __restrict__ out,
    const float* __restrict__ pjw, const float* __restrict__ temp)
{
    extern __shared__ unsigned smk[];
    unsigned* sVh = smk;
    unsigned* sVl = smk + 128*ROWW;
    float* sM = (float*)(smk + 2*128*ROWW);
    float* sA = sM + 4096;
    const int tid = threadIdx.x, wid = tid >> 5, lane = tid & 31;
    const int mb = wid & 3, nh = wid >> 2;
    const int grow = lane >> 2, t = lane & 3;
    const int b = blockIdx.x & 7;
    const int sub = blockIdx.x >> 3;
    const int bstride = gridDim.x >> 3;

    if (tid < 64){
        const int h = tid >> 4;
        const float tv = __ldg(temp + h);
        const float inq = tv / fmaxf(sqrtf(g_qss[b*64 + tid]), EPSN);
        const float* gr = g_gram + (b*4 + h)*256 + (tid & 15)*16;
        float l[16]; float mx = -1e30f;
        #pragma unroll
        for (int d = 0; d < 16; ++d){
            l[d] = gr[d] * inq / fmaxf(sqrtf(g_kss[b*64 + h*16 + d]), EPSN);
            mx = fmaxf(mx, l[d]);
        }
        float ssum = 0.f;
        #pragma unroll
        for (int d = 0; d < 16; ++d){ l[d] = __expf(l[d] - mx); ssum += l[d]; }
        const float inv = 1.f / ssum;
        #pragma unroll
        for (int d = 0; d < 16; ++d) sA[tid*16 + d] = l[d] * inv;
    }
    __syncthreads();
    for (int idx = tid; idx < 4096; idx += 256){
        const int o = idx >> 6, cd = idx & 63, h = cd >> 4, d = cd & 15;
        float s = 0.f;
        #pragma unroll
        for (int ci = 0; ci < 16; ++ci)
            s += __ldg(pjw + o*64 + h*16 + ci) * sA[(h*16 + ci)*16 + d];
        sM[idx] = s;
    }
    __syncthreads();

    unsigned aMh[4][4], aMl[4][4];
    {
        const int r0 = mb*16 + grow;
        #pragma unroll
        for (int cc = 0; cc < 4; ++cc){
            const int k0 = cc*16 + t*2;
            float w00 = sM[r0*64 + k0],       w01 = sM[r0*64 + k0 + 1];
            float w10 = sM[(r0+8)*64 + k0],   w11 = sM[(r0+8)*64 + k0 + 1];
            float w20 = sM[r0*64 + k0 + 8],   w21 = sM[r0*64 + k0 + 9];
            float w30 = sM[(r0+8)*64 + k0+8], w31 = sM[(r0+8)*64 + k0 + 9];
            aMh[cc][0] = pkbf(w00, w01); aMl[cc][0] = pkbf(w00 - bf16f(w00), w01 - bf16f(w01));
            aMh[cc][1] = pkbf(w10, w11); aMl[cc][1] = pkbf(w10 - bf16f(w10), w11 - bf16f(w11));
            aMh[cc][2] = pkbf(w20, w21); aMl[cc][2] = pkbf(w20 - bf16f(w20), w21 - bf16f(w21));
            aMh[cc][3] = pkbf(w30, w31); aMl[cc][3] = pkbf(w30 - bf16f(w30), w31 - bf16f(w31));
        }
    }

    for (int tt = sub; tt < 512; tt += bstride){
        const size_t pxb = (size_t)tt << 7;
        const float* gv = g_v + (size_t)b*64*HW + pxb;

        #pragma unroll
        for (int j = 0; j < 8; ++j){
            const int idx = tid + j*256;
            const int ch = idx & 63;
            const int px0 = (idx >> 6) << 2;
            float4 v = __ldg((const float4*)(gv + (size_t)ch*HW + px0));
            float o0 = __shfl_xor_sync(0xffffffffu, v.x, 1);
            float o1 = __shfl_xor_sync(0xffffffffu, v.y, 1);
            float o2 = __shfl_xor_sync(0xffffffffu, v.z, 1);
            float o3 = __shfl_xor_sync(0xffffffffu, v.w, 1);
            const int cp = ch >> 1;
            if (!(ch & 1)){
                float h0 = bf16f(v.x), h1 = bf16f(v.y);
                float p0 = bf16f(o0),  p1 = bf16f(o1);
                sVh[(px0    )*ROWW + cp] = pkbf(h0, p0);
                sVh[(px0 + 1)*ROWW + cp] = pkbf(h1, p1);
                sVl[(px0    )*ROWW + cp] = pkbf(v.x - h0, o0 - p0);
                sVl[(px0 + 1)*ROWW + cp] = pkbf(v.y - h1, o1 - p1);
            } else {
                float h2 = bf16f(v.z), h3 = bf16f(v.w);
                float p2 = bf16f(o2),  p3 = bf16f(o3);
                sVh[(px0 + 2)*ROWW + cp] = pkbf(p2, h2);
                sVh[(px0 + 3)*ROWW + cp] = pkbf(p3, h3);
                sVl[(px0 + 2)*ROWW + cp] = pkbf(o2 - p2, v.z - h2);
                sVl[(px0 + 3)*ROWW + cp] = pkbf(o3 - p3, v.w - h3);
            }
        }
        __syncthreads();

        #pragma unroll
        for (int nt = 0; nt < 8; ++nt){
            const int nb = nh*64 + nt*8;
            const int nrow = nb + grow;
            float acv[4] = {0.f, 0.f, 0.f, 0.f};
            #pragma unroll
            for (int cc = 0; cc < 4; ++cc){
                unsigned bH[2], bL[2];
                const int w0 = nrow*ROWW + cc*8 + t;
                bH[0] = sVh[w0]; bH[1] = sVh[w0 + 4];
                bL[0] = sVl[w0]; bL[1] = sVl[w0 + 4];
                mma16816(acv, aMh[cc], bH);
                mma16816(acv, aMh[cc], bL);
                mma16816(acv, aMl[cc], bH);
            }
            const int ch = b*64 + mb*16 + grow;
            const size_t pxa = pxb + nb + 2*t;
            float2 v01; v01.x = acv[0]; v01.y = acv[1];
            float2 v23; v23.x = acv[2]; v23.y = acv[3];
            *(float2*)(out + (size_t)ch*HW + pxa)       = v01;
            *(float2*)(out + (size_t)(ch + 8)*HW + pxa) = v23;
        }
        __syncthreads();
    }
}

// ---------------- launch ----------------
extern "C" void kernel_launch(void* const* d_in, const int* in_sizes, int n_in,
                              void* d_out, int out_size)
{
    (void)in_sizes; (void)n_in; (void)out_size;
    const float* dg   = (const float*)d_in[0];
    const float* xin  = (const float*)d_in[1];
    const float* yin  = (const float*)d_in[2];
    const float* q1w  = (const float*)d_in[3];
    const float* q2w  = (const float*)d_in[4];
    const float* qdw  = (const float*)d_in[5];
    const float* kvw  = (const float*)d_in[6];
    const float* kvdw = (const float*)d_in[7];
    const float* pjw  = (const float*)d_in[8];
    const float* temp = (const float*)d_in[9];
    float* out = (float*)d_out;

    cudaFuncSetAttribute(k1a_mma, cudaFuncAttributeMaxDynamicSharedMemorySize, 36864);
    cudaFuncSetAttribute(k1b_mma, cudaFuncAttributeMaxDynamicSharedMemorySize, 36864);
    cudaFuncSetAttribute(k2qk,    cudaFuncAttributeMaxDynamicSharedMemorySize, 74240);
    cudaFuncSetAttribute(k4_mma,  cudaFuncAttributeMaxDynamicSharedMemorySize, 57344);

    k0_init<<<32, 256>>>();
    k1a_mma<<<444, 256, 36864>>>(dg, xin, q1w, q2w);
    k1b_mma<<<444, 256, 36864>>>(yin, kvw);
    k2v_dw <<<dim3(8, 64, 8), 256>>>(kvdw);
    k2qk   <<<dim3(64, 4, 8), 256, 74240>>>(qdw, kvdw);
    k4_mma <<<440, 256, 57344>>>(out, pjw, temp);
}